// round 2
// baseline (speedup 1.0000x reference)
#include <cuda_runtime.h>

#define BB 4
#define C 64
#define IC 16
#define H 128
#define W 128
#define DH 64
#define DW 64
#define NN 4096  // DH*DW

// ---------------- scratch (device globals; no allocation) ----------------
__device__ float g_q[BB*NN*IC];
__device__ float g_k[BB*NN*IC];
__device__ float g_v[BB*NN*IC];
__device__ float g_y[BB*IC*NN];
__device__ float g_sum[C];
__device__ float g_sqs[C];
__device__ float g_ab[2*C];   // scale, shift

// FMA-only exp: 2^r poly (deg 5) + exponent splice.
__device__ __forceinline__ float fexp(float x) {
    float t = x * 1.4426950408889634f;
    float nf = rintf(t);
    float r  = t - nf;
    float p = 1.3333558e-3f;
    p = fmaf(p, r, 9.6181291e-3f);
    p = fmaf(p, r, 5.5504109e-2f);
    p = fmaf(p, r, 2.4022651e-1f);
    p = fmaf(p, r, 6.9314718e-1f);
    p = fmaf(p, r, 1.0f);
    int e = (int)nf;
    float s = __int_as_float((e + 127) << 23);
    return p * s;
}

// ---------------- Kernel 0: zero stats ----------------
__global__ void zero_stats() {
    int t = threadIdx.x;
    if (t < C) { g_sum[t] = 0.f; g_sqs[t] = 0.f; }
}

// ---------------- Kernel 1: downsample (odd-pixel pick) + Q/K/V projections ----------------
// grid (128, BB), block 128. Tile = 32 downsampled pixels.
__global__ void qkv_kernel(const float* __restrict__ x,
                           const float* __restrict__ g_w,  const float* __restrict__ g_b,
                           const float* __restrict__ th_w, const float* __restrict__ th_b,
                           const float* __restrict__ ph_w, const float* __restrict__ ph_b) {
    __shared__ float xd_s[C][32];
    __shared__ float w_s[48][C];
    __shared__ float b_s[48];
    int b = blockIdx.y, tile = blockIdx.x, tid = threadIdx.x;

    for (int idx = tid; idx < 48 * C; idx += 128) {
        int o = idx >> 6, c = idx & 63;
        float w;
        if (o < 16)      w = th_w[o * C + c];
        else if (o < 32) w = ph_w[(o - 16) * C + c];
        else             w = g_w[(o - 32) * C + c];
        w_s[o][c] = w;
    }
    if (tid < 48)
        b_s[tid] = (tid < 16) ? th_b[tid] : ((tid < 32) ? ph_b[tid - 16] : g_b[tid - 32]);

    int n0 = tile * 32;
    for (int idx = tid; idx < C * 32; idx += 128) {
        int c = idx >> 5, p = idx & 31;
        int n = n0 + p;
        int i = n >> 6, j = n & 63;
        // reference resample: sample_f = 2o+1 exactly -> pick x[2i+1][2j+1]
        xd_s[c][p] = x[(((b * C + c) * H + 2 * i + 1) * W) + 2 * j + 1];
    }
    __syncthreads();

    int p = tid & 31, og = tid >> 5;
    int n = n0 + p;
    #pragma unroll
    for (int r = 0; r < 12; r++) {
        int o = og + 4 * r;
        float a0 = b_s[o], a1 = 0.f, a2 = 0.f, a3 = 0.f;
        #pragma unroll
        for (int c = 0; c < C; c += 4) {
            a0 = fmaf(w_s[o][c + 0], xd_s[c + 0][p], a0);
            a1 = fmaf(w_s[o][c + 1], xd_s[c + 1][p], a1);
            a2 = fmaf(w_s[o][c + 2], xd_s[c + 2][p], a2);
            a3 = fmaf(w_s[o][c + 3], xd_s[c + 3][p], a3);
        }
        float acc = (a0 + a1) + (a2 + a3);
        if (o < 16)      g_q[(b * NN + n) * IC + o]        = acc;
        else if (o < 32) g_k[(b * NN + n) * IC + (o - 16)] = acc;
        else             g_v[(b * NN + n) * IC + (o - 32)] = acc;
    }
}

// ---------------- Kernel 2: fused attention (no NxN materialization) ----------------
// grid (64, BB), block 256. 64 queries/block; 4 threads per query split keys mod 4.
#define TK 128
#define KPAD 20
__global__ void attn_kernel() {
    __shared__ float ks[TK * KPAD];
    __shared__ float vs[TK * KPAD];
    int b = blockIdx.y;
    int t = threadIdx.x;
    int ql = t >> 2, sl = t & 3;
    int n = blockIdx.x * 64 + ql;

    const float* qp = g_q + (b * NN + n) * IC;
    float q[16];
    #pragma unroll
    for (int i = 0; i < 16; i += 4) {
        float4 f = *(const float4*)(qp + i);
        q[i] = f.x; q[i + 1] = f.y; q[i + 2] = f.z; q[i + 3] = f.w;
    }
    float acc[16];
    #pragma unroll
    for (int i = 0; i < 16; i++) acc[i] = 0.f;
    float denom = 0.f;

    const float* kb = g_k + b * NN * IC;
    const float* vb = g_v + b * NN * IC;

    for (int kt = 0; kt < NN; kt += TK) {
        {
            int row = t >> 1, half = (t & 1) * 8;
            const float* src = kb + (kt + row) * IC + half;
            float4 a = *(const float4*)(src);
            float4 c2 = *(const float4*)(src + 4);
            *(float4*)(ks + row * KPAD + half)     = a;
            *(float4*)(ks + row * KPAD + half + 4) = c2;
            src = vb + (kt + row) * IC + half;
            a  = *(const float4*)(src);
            c2 = *(const float4*)(src + 4);
            *(float4*)(vs + row * KPAD + half)     = a;
            *(float4*)(vs + row * KPAD + half + 4) = c2;
        }
        __syncthreads();
        #pragma unroll 2
        for (int m = 0; m < TK / 4; m++) {
            int j = 4 * m + sl;
            const float* kr = ks + j * KPAD;
            float4 k0 = *(const float4*)(kr);
            float4 k1 = *(const float4*)(kr + 4);
            float4 k2 = *(const float4*)(kr + 8);
            float4 k3 = *(const float4*)(kr + 12);
            float sA = q[0] * k0.x, sB = q[1] * k0.y, sC = q[2] * k0.z, sD = q[3] * k0.w;
            sA = fmaf(q[4],  k1.x, sA); sB = fmaf(q[5],  k1.y, sB);
            sC = fmaf(q[6],  k1.z, sC); sD = fmaf(q[7],  k1.w, sD);
            sA = fmaf(q[8],  k2.x, sA); sB = fmaf(q[9],  k2.y, sB);
            sC = fmaf(q[10], k2.z, sC); sD = fmaf(q[11], k2.w, sD);
            sA = fmaf(q[12], k3.x, sA); sB = fmaf(q[13], k3.y, sB);
            sC = fmaf(q[14], k3.z, sC); sD = fmaf(q[15], k3.w, sD);
            float s = (sA + sB) + (sC + sD);
            float e = fexp(s);
            denom += e;
            const float* vr = vs + j * KPAD;
            float4 v0 = *(const float4*)(vr);
            float4 v1 = *(const float4*)(vr + 4);
            float4 v2 = *(const float4*)(vr + 8);
            float4 v3 = *(const float4*)(vr + 12);
            acc[0]  = fmaf(e, v0.x, acc[0]);  acc[1]  = fmaf(e, v0.y, acc[1]);
            acc[2]  = fmaf(e, v0.z, acc[2]);  acc[3]  = fmaf(e, v0.w, acc[3]);
            acc[4]  = fmaf(e, v1.x, acc[4]);  acc[5]  = fmaf(e, v1.y, acc[5]);
            acc[6]  = fmaf(e, v1.z, acc[6]);  acc[7]  = fmaf(e, v1.w, acc[7]);
            acc[8]  = fmaf(e, v2.x, acc[8]);  acc[9]  = fmaf(e, v2.y, acc[9]);
            acc[10] = fmaf(e, v2.z, acc[10]); acc[11] = fmaf(e, v2.w, acc[11]);
            acc[12] = fmaf(e, v3.x, acc[12]); acc[13] = fmaf(e, v3.y, acc[13]);
            acc[14] = fmaf(e, v3.z, acc[14]); acc[15] = fmaf(e, v3.w, acc[15]);
        }
        __syncthreads();
    }

    #pragma unroll
    for (int i = 0; i < 16; i++) {
        acc[i] += __shfl_xor_sync(0xffffffffu, acc[i], 1);
        acc[i] += __shfl_xor_sync(0xffffffffu, acc[i], 2);
    }
    denom += __shfl_xor_sync(0xffffffffu, denom, 1);
    denom += __shfl_xor_sync(0xffffffffu, denom, 2);

    if (sl == 0) {
        float inv = 1.0f / denom;
        float* yo = g_y + b * IC * NN + n;
        #pragma unroll
        for (int i = 0; i < 16; i++) yo[i * NN] = acc[i] * inv;
    }
}

// ---------------- Kernel 3: upsample + out-proj + residual + BN stats ----------------
// grid 1024, block 256. Tile = 64 output pixels of one row (half row), all 64 channels.
__global__ void fuse_kernel(const float* __restrict__ x,
                            const float* __restrict__ out_w, const float* __restrict__ out_b,
                            float* __restrict__ out) {
    __shared__ float yup[IC][64];
    __shared__ float ssum[C], ssq[C];
    int bx = blockIdx.x;           // 0..1023
    int b  = bx >> 8;
    int row = (bx >> 1) & 127;
    int jh = bx & 1;
    int t = threadIdx.x;
    if (t < C) { ssum[t] = 0.f; ssq[t] = 0.f; }

    // reference resample: sample_f = 0.5*o - 0.5 (edge weights renormalize == clamp)
    float fi = 0.5f * row - 0.5f;
    int r0 = (int)floorf(fi);
    float wi = fi - (float)r0;
    int r1 = min(r0 + 1, DH - 1);
    r0 = max(r0, 0);

    for (int idx = t; idx < IC * 64; idx += 256) {
        int ic = idx >> 6, p = idx & 63;
        int j = jh * 64 + p;
        float fj = 0.5f * j - 0.5f;
        int c0 = (int)floorf(fj);
        float wj = fj - (float)c0;
        int c1 = min(c0 + 1, DW - 1);
        c0 = max(c0, 0);
        const float* yp = g_y + (b * IC + ic) * NN;
        float v00 = yp[r0 * DW + c0], v01 = yp[r0 * DW + c1];
        float v10 = yp[r1 * DW + c0], v11 = yp[r1 * DW + c1];
        yup[ic][p] = (1.f - wi) * fmaf(wj, v01 - v00, v00)
                   +        wi  * fmaf(wj, v11 - v10, v10);
    }
    __syncthreads();

    int p = t & 63, cg = t >> 6;
    float yr[16];
    #pragma unroll
    for (int i2 = 0; i2 < 16; i2++) yr[i2] = yup[i2][p];
    int lane = t & 31;

    for (int k = 0; k < 16; k++) {
        int c = cg * 16 + k;
        float a0 = out_b[c], a1 = 0.f, a2 = 0.f, a3 = 0.f;
        #pragma unroll
        for (int i2 = 0; i2 < 16; i2 += 4) {
            a0 = fmaf(out_w[c * IC + i2 + 0], yr[i2 + 0], a0);
            a1 = fmaf(out_w[c * IC + i2 + 1], yr[i2 + 1], a1);
            a2 = fmaf(out_w[c * IC + i2 + 2], yr[i2 + 2], a2);
            a3 = fmaf(out_w[c * IC + i2 + 3], yr[i2 + 3], a3);
        }
        float acc = (a0 + a1) + (a2 + a3);
        int gi = ((b * C + c) * H + row) * W + jh * 64 + p;
        float z = x[gi] + acc;
        out[gi] = z;
        float s1 = z, s2 = z * z;
        #pragma unroll
        for (int off = 16; off; off >>= 1) {
            s1 += __shfl_down_sync(0xffffffffu, s1, off);
            s2 += __shfl_down_sync(0xffffffffu, s2, off);
        }
        if (lane == 0) { atomicAdd(&ssum[c], s1); atomicAdd(&ssq[c], s2); }
    }
    __syncthreads();
    if (t < C) {
        atomicAdd(&g_sum[t], ssum[t]);
        atomicAdd(&g_sqs[t], ssq[t]);
    }
}

// ---------------- Kernel 4: finalize BN scale/shift ----------------
__global__ void finalize_kernel(const float* __restrict__ bn_gamma,
                                const float* __restrict__ bn_beta) {
    int c = threadIdx.x;
    if (c < C) {
        float npix = (float)(BB * H * W);
        float mean = g_sum[c] / npix;
        float var  = g_sqs[c] / npix - mean * mean;
        float rstd = rsqrtf(var + 1e-5f);
        float a = bn_gamma[c] * rstd;
        g_ab[c] = a;
        g_ab[C + c] = bn_beta[c] - mean * a;
    }
}

// ---------------- Kernel 5: apply BN affine in place ----------------
__global__ void norm_kernel(float* __restrict__ out) {
    int e4 = blockIdx.x * 256 + threadIdx.x;   // float4 index; total 1048576
    int e = e4 * 4;
    int c = (e >> 14) & 63;                    // H*W = 16384
    float a = g_ab[c], sh = g_ab[C + c];
    float4 v = *(float4*)(out + e);
    v.x = fmaf(v.x, a, sh);
    v.y = fmaf(v.y, a, sh);
    v.z = fmaf(v.z, a, sh);
    v.w = fmaf(v.w, a, sh);
    *(float4*)(out + e) = v;
}

// ---------------- launch ----------------
extern "C" void kernel_launch(void* const* d_in, const int* in_sizes, int n_in,
                              void* d_out, int out_size) {
    const float* x        = (const float*)d_in[0];
    const float* g_w      = (const float*)d_in[1];
    const float* g_b      = (const float*)d_in[2];
    const float* theta_w  = (const float*)d_in[3];
    const float* theta_b  = (const float*)d_in[4];
    const float* phi_w    = (const float*)d_in[5];
    const float* phi_b    = (const float*)d_in[6];
    const float* out_w    = (const float*)d_in[7];
    const float* out_b    = (const float*)d_in[8];
    const float* bn_gamma = (const float*)d_in[9];
    const float* bn_beta  = (const float*)d_in[10];
    float* out = (float*)d_out;

    zero_stats<<<1, 64>>>();
    qkv_kernel<<<dim3(128, BB), 128>>>(x, g_w, g_b, theta_w, theta_b, phi_w, phi_b);
    attn_kernel<<<dim3(64, BB), 256>>>();
    fuse_kernel<<<1024, 256>>>(x, out_w, out_b, out);
    finalize_kernel<<<1, 64>>>(bn_gamma, bn_beta);
    norm_kernel<<<4096, 256>>>(out);
}

// round 3
// speedup vs baseline: 1.9721x; 1.9721x over previous
#include <cuda_runtime.h>

#define BB 4
#define C 64
#define IC 16
#define H 128
#define W 128
#define DH 64
#define DW 64
#define NN 4096  // DH*DW

// ---------------- scratch (device globals; no allocation) ----------------
__device__ __align__(16) float g_q[BB*NN*IC];
__device__ __align__(16) float g_k[BB*NN*IC];
__device__ __align__(16) float g_v[BB*NN*IC];
__device__ __align__(16) float g_y[BB*IC*NN];
__device__ float g_sum[C];
__device__ float g_sqs[C];
__device__ float g_ab[2*C];   // scale, shift

typedef unsigned long long ull;

__device__ __forceinline__ ull pk2(float x, float y) {
    ull r;
    asm("mov.b64 %0, {%1,%2};" : "=l"(r) : "f"(x), "f"(y));
    return r;
}
__device__ __forceinline__ void upk2(ull v, float& lo, float& hi) {
    asm("mov.b64 {%0,%1}, %2;" : "=f"(lo), "=f"(hi) : "l"(v));
}
__device__ __forceinline__ void fma2(ull& d, ull a, ull b) {
    asm("fma.rn.f32x2 %0, %1, %2, %3;" : "=l"(d) : "l"(a), "l"(b), "l"(d));
}

// ---------------- Kernel 0: zero stats ----------------
__global__ void zero_stats() {
    int t = threadIdx.x;
    if (t < C) { g_sum[t] = 0.f; g_sqs[t] = 0.f; }
}

// ---------------- Kernel 1: downsample (odd-pixel pick) + Q/K/V projections ----------------
__global__ void qkv_kernel(const float* __restrict__ x,
                           const float* __restrict__ g_w,  const float* __restrict__ g_b,
                           const float* __restrict__ th_w, const float* __restrict__ th_b,
                           const float* __restrict__ ph_w, const float* __restrict__ ph_b) {
    __shared__ float xd_s[C][32];
    __shared__ float w_s[48][C];
    __shared__ float b_s[48];
    int b = blockIdx.y, tile = blockIdx.x, tid = threadIdx.x;

    for (int idx = tid; idx < 48 * C; idx += 128) {
        int o = idx >> 6, c = idx & 63;
        float w;
        if (o < 16)      w = th_w[o * C + c];
        else if (o < 32) w = ph_w[(o - 16) * C + c];
        else             w = g_w[(o - 32) * C + c];
        w_s[o][c] = w;
    }
    if (tid < 48)
        b_s[tid] = (tid < 16) ? th_b[tid] : ((tid < 32) ? ph_b[tid - 16] : g_b[tid - 32]);

    int n0 = tile * 32;
    for (int idx = tid; idx < C * 32; idx += 128) {
        int c = idx >> 5, p = idx & 31;
        int n = n0 + p;
        int i = n >> 6, j = n & 63;
        xd_s[c][p] = x[(((b * C + c) * H + 2 * i + 1) * W) + 2 * j + 1];
    }
    __syncthreads();

    int p = tid & 31, og = tid >> 5;
    int n = n0 + p;
    #pragma unroll
    for (int r = 0; r < 12; r++) {
        int o = og + 4 * r;
        float a0 = b_s[o], a1 = 0.f, a2 = 0.f, a3 = 0.f;
        #pragma unroll
        for (int c = 0; c < C; c += 4) {
            a0 = fmaf(w_s[o][c + 0], xd_s[c + 0][p], a0);
            a1 = fmaf(w_s[o][c + 1], xd_s[c + 1][p], a1);
            a2 = fmaf(w_s[o][c + 2], xd_s[c + 2][p], a2);
            a3 = fmaf(w_s[o][c + 3], xd_s[c + 3][p], a3);
        }
        float acc = (a0 + a1) + (a2 + a3);
        if (o < 16)      g_q[(b * NN + n) * IC + o]        = acc;
        else if (o < 32) g_k[(b * NN + n) * IC + (o - 16)] = acc;
        else             g_v[(b * NN + n) * IC + (o - 32)] = acc;
    }
}

// ---------------- Kernel 2: register-blocked flash attention ----------------
// grid (64, BB), block 256. 64 queries/block. Thread tile: 4 queries x 8 keys.
// Threads: qg = t&15 (16 query groups of 4), kg = t>>4 (16 key groups of 8). TK=128.
#define TK 128
#define KSP 132   // ks row pad (floats); 132*4B=528B, 16B-aligned rows
__global__ __launch_bounds__(256) void attn_kernel() {
    __shared__ __align__(16) float qs[IC][64];
    __shared__ __align__(16) float ks[IC][KSP];
    __shared__ __align__(16) float vs[TK][IC];
    __shared__ float red[16][65];
    __shared__ float dsm[64];

    int b = blockIdx.y;
    int t = threadIdx.x;
    int qg = t & 15, kg = t >> 4;
    int n0 = blockIdx.x * 64;

    // load Q tile transposed: qs[ic][query]
    {
        int qq = t >> 2, ch = t & 3;
        float4 f = *(const float4*)(g_q + (b * NN + n0 + qq) * IC + ch * 4);
        qs[ch * 4 + 0][qq] = f.x; qs[ch * 4 + 1][qq] = f.y;
        qs[ch * 4 + 2][qq] = f.z; qs[ch * 4 + 3][qq] = f.w;
    }

    ull Y[4][8];
    #pragma unroll
    for (int q = 0; q < 4; q++)
        #pragma unroll
        for (int i = 0; i < 8; i++) Y[q][i] = 0ull;
    float den[4] = {0.f, 0.f, 0.f, 0.f};

    const float* kb = g_k + b * NN * IC;
    const float* vb = g_v + b * NN * IC;

    for (int kt = 0; kt < NN; kt += TK) {
        __syncthreads();
        // stage K (transposed) and V (row-major)
        {
            const float4* ksrc = (const float4*)(kb + kt * IC);
            const float4* vsrc = (const float4*)(vb + kt * IC);
            #pragma unroll
            for (int i = 0; i < 2; i++) {
                int idx = t + i * 256;          // 0..511 float4 chunks
                int key = idx >> 2, ch = idx & 3;
                float4 kv = ksrc[idx];
                ks[ch * 4 + 0][key] = kv.x; ks[ch * 4 + 1][key] = kv.y;
                ks[ch * 4 + 2][key] = kv.z; ks[ch * 4 + 3][key] = kv.w;
                ((float4*)vs)[idx] = vsrc[idx];
            }
        }
        __syncthreads();

        // score tile: S[q][kpair] over 16 ic
        ull S[4][4];
        #pragma unroll
        for (int q = 0; q < 4; q++)
            #pragma unroll
            for (int p = 0; p < 4; p++) S[q][p] = 0ull;

        #pragma unroll
        for (int ic = 0; ic < IC; ic++) {
            float4 qv = *(const float4*)&qs[ic][qg * 4];
            ulonglong2 ka = *(const ulonglong2*)&ks[ic][kg * 8];
            ulonglong2 kc = *(const ulonglong2*)&ks[ic][kg * 8 + 4];
            ull q0 = pk2(qv.x, qv.x), q1 = pk2(qv.y, qv.y);
            ull q2 = pk2(qv.z, qv.z), q3 = pk2(qv.w, qv.w);
            fma2(S[0][0], q0, ka.x); fma2(S[0][1], q0, ka.y);
            fma2(S[0][2], q0, kc.x); fma2(S[0][3], q0, kc.y);
            fma2(S[1][0], q1, ka.x); fma2(S[1][1], q1, ka.y);
            fma2(S[1][2], q1, kc.x); fma2(S[1][3], q1, kc.y);
            fma2(S[2][0], q2, ka.x); fma2(S[2][1], q2, ka.y);
            fma2(S[2][2], q2, kc.x); fma2(S[2][3], q2, kc.y);
            fma2(S[3][0], q3, ka.x); fma2(S[3][1], q3, ka.y);
            fma2(S[3][2], q3, kc.x); fma2(S[3][3], q3, kc.y);
        }

        // exp + PV, two keys (one S pair) at a time
        #pragma unroll
        for (int p = 0; p < 4; p++) {
            float e0[4], e1[4];
            #pragma unroll
            for (int q = 0; q < 4; q++) {
                float lo, hi;
                upk2(S[q][p], lo, hi);
                e0[q] = __expf(lo);
                e1[q] = __expf(hi);
                den[q] += e0[q] + e1[q];
            }
            const ulonglong2* vp0 = (const ulonglong2*)&vs[kg * 8 + 2 * p][0];
            ulonglong2 va = vp0[0], vb2 = vp0[1], vc = vp0[2], vd = vp0[3];
            #pragma unroll
            for (int q = 0; q < 4; q++) {
                ull ee = pk2(e0[q], e0[q]);
                fma2(Y[q][0], ee, va.x);  fma2(Y[q][1], ee, va.y);
                fma2(Y[q][2], ee, vb2.x); fma2(Y[q][3], ee, vb2.y);
                fma2(Y[q][4], ee, vc.x);  fma2(Y[q][5], ee, vc.y);
                fma2(Y[q][6], ee, vd.x);  fma2(Y[q][7], ee, vd.y);
            }
            const ulonglong2* vp1 = (const ulonglong2*)&vs[kg * 8 + 2 * p + 1][0];
            va = vp1[0]; vb2 = vp1[1]; vc = vp1[2]; vd = vp1[3];
            #pragma unroll
            for (int q = 0; q < 4; q++) {
                ull ee = pk2(e1[q], e1[q]);
                fma2(Y[q][0], ee, va.x);  fma2(Y[q][1], ee, va.y);
                fma2(Y[q][2], ee, vb2.x); fma2(Y[q][3], ee, vb2.y);
                fma2(Y[q][4], ee, vc.x);  fma2(Y[q][5], ee, vc.y);
                fma2(Y[q][6], ee, vd.x);  fma2(Y[q][7], ee, vd.y);
            }
        }
    }

    // ---- reduce across 16 key-groups ----
    __syncthreads();
    // denominators
    #pragma unroll
    for (int q = 0; q < 4; q++) red[kg][qg * 4 + q] = den[q];
    __syncthreads();
    if (t < 64) {
        float d = 0.f;
        #pragma unroll
        for (int k2 = 0; k2 < 16; k2++) d += red[k2][t];
        dsm[t] = 1.0f / d;
    }
    // Y reduction, one ic at a time
    #pragma unroll
    for (int ic = 0; ic < IC; ic++) {
        __syncthreads();
        int p = ic >> 1, hf = ic & 1;
        #pragma unroll
        for (int q = 0; q < 4; q++) {
            float lo, hi;
            upk2(Y[q][p], lo, hi);
            red[kg][qg * 4 + q] = hf ? hi : lo;
        }
        __syncthreads();
        if (t < 64) {
            float s = 0.f;
            #pragma unroll
            for (int k2 = 0; k2 < 16; k2++) s += red[k2][t];
            g_y[(b * IC + ic) * NN + n0 + t] = s * dsm[t];
        }
    }
}

// ---------------- Kernel 3: upsample + out-proj + residual (no stats) ----------------
__global__ void fuse_kernel(const float* __restrict__ x,
                            const float* __restrict__ out_w, const float* __restrict__ out_b,
                            float* __restrict__ out) {
    __shared__ float yup[IC][64];
    __shared__ float wsm[C * IC];
    __shared__ float bsm[C];
    int bx = blockIdx.x;
    int b  = bx >> 8;
    int row = (bx >> 1) & 127;
    int jh = bx & 1;
    int t = threadIdx.x;

    ((float4*)wsm)[t] = ((const float4*)out_w)[t];   // 256*16B = 1024 floats
    if (t < C) bsm[t] = out_b[t];

    float fi = 0.5f * row - 0.5f;
    int r0 = (int)floorf(fi);
    float wi = fi - (float)r0;
    int r1 = min(r0 + 1, DH - 1);
    r0 = max(r0, 0);

    for (int idx = t; idx < IC * 64; idx += 256) {
        int ic = idx >> 6, p = idx & 63;
        int j = jh * 64 + p;
        float fj = 0.5f * j - 0.5f;
        int c0 = (int)floorf(fj);
        float wj = fj - (float)c0;
        int c1 = min(c0 + 1, DW - 1);
        c0 = max(c0, 0);
        const float* yp = g_y + (b * IC + ic) * NN;
        float v00 = yp[r0 * DW + c0], v01 = yp[r0 * DW + c1];
        float v10 = yp[r1 * DW + c0], v11 = yp[r1 * DW + c1];
        yup[ic][p] = (1.f - wi) * fmaf(wj, v01 - v00, v00)
                   +        wi  * fmaf(wj, v11 - v10, v10);
    }
    __syncthreads();

    int p = t & 63, cg = t >> 6;
    float yr[16];
    #pragma unroll
    for (int i2 = 0; i2 < 16; i2++) yr[i2] = yup[i2][p];

    #pragma unroll
    for (int k = 0; k < 16; k++) {
        int c = cg * 16 + k;
        const float* wr = wsm + c * IC;
        float a0 = bsm[c], a1 = 0.f, a2 = 0.f, a3 = 0.f;
        #pragma unroll
        for (int i2 = 0; i2 < 16; i2 += 4) {
            a0 = fmaf(wr[i2 + 0], yr[i2 + 0], a0);
            a1 = fmaf(wr[i2 + 1], yr[i2 + 1], a1);
            a2 = fmaf(wr[i2 + 2], yr[i2 + 2], a2);
            a3 = fmaf(wr[i2 + 3], yr[i2 + 3], a3);
        }
        float acc = (a0 + a1) + (a2 + a3);
        int gi = ((b * C + c) * H + row) * W + jh * 64 + p;
        out[gi] = x[gi] + acc;
    }
}

// ---------------- Kernel 3b: BN batch stats over out ----------------
// grid (C, 8), block 256. Each block: one channel, 1/8 of H*W, all batches.
__global__ void stats_kernel(const float* __restrict__ out) {
    __shared__ float s1s[8], s2s[8];
    int c = blockIdx.x, sl = blockIdx.y, t = threadIdx.x;
    float s1 = 0.f, s2 = 0.f;
    #pragma unroll
    for (int b = 0; b < BB; b++) {
        const float4* p = (const float4*)(out + (((b * C + c) << 14) + sl * 2048));
        float4 v = p[t];
        s1 += (v.x + v.y) + (v.z + v.w);
        s2 += fmaf(v.x, v.x, v.y * v.y) + fmaf(v.z, v.z, v.w * v.w);
        v = p[t + 256];
        s1 += (v.x + v.y) + (v.z + v.w);
        s2 += fmaf(v.x, v.x, v.y * v.y) + fmaf(v.z, v.z, v.w * v.w);
    }
    #pragma unroll
    for (int off = 16; off; off >>= 1) {
        s1 += __shfl_down_sync(0xffffffffu, s1, off);
        s2 += __shfl_down_sync(0xffffffffu, s2, off);
    }
    int w = t >> 5;
    if ((t & 31) == 0) { s1s[w] = s1; s2s[w] = s2; }
    __syncthreads();
    if (t == 0) {
        float a1 = 0.f, a2 = 0.f;
        #pragma unroll
        for (int i = 0; i < 8; i++) { a1 += s1s[i]; a2 += s2s[i]; }
        atomicAdd(&g_sum[c], a1);
        atomicAdd(&g_sqs[c], a2);
    }
}

// ---------------- Kernel 4: finalize BN scale/shift ----------------
__global__ void finalize_kernel(const float* __restrict__ bn_gamma,
                                const float* __restrict__ bn_beta) {
    int c = threadIdx.x;
    if (c < C) {
        float npix = (float)(BB * H * W);
        float mean = g_sum[c] / npix;
        float var  = g_sqs[c] / npix - mean * mean;
        float rstd = rsqrtf(var + 1e-5f);
        float a = bn_gamma[c] * rstd;
        g_ab[c] = a;
        g_ab[C + c] = bn_beta[c] - mean * a;
    }
}

// ---------------- Kernel 5: apply BN affine in place ----------------
__global__ void norm_kernel(float* __restrict__ out) {
    int e4 = blockIdx.x * 256 + threadIdx.x;
    int e = e4 * 4;
    int c = (e >> 14) & 63;
    float a = g_ab[c], sh = g_ab[C + c];
    float4 v = *(float4*)(out + e);
    v.x = fmaf(v.x, a, sh);
    v.y = fmaf(v.y, a, sh);
    v.z = fmaf(v.z, a, sh);
    v.w = fmaf(v.w, a, sh);
    *(float4*)(out + e) = v;
}

// ---------------- launch ----------------
extern "C" void kernel_launch(void* const* d_in, const int* in_sizes, int n_in,
                              void* d_out, int out_size) {
    const float* x        = (const float*)d_in[0];
    const float* g_w      = (const float*)d_in[1];
    const float* g_b      = (const float*)d_in[2];
    const float* theta_w  = (const float*)d_in[3];
    const float* theta_b  = (const float*)d_in[4];
    const float* phi_w    = (const float*)d_in[5];
    const float* phi_b    = (const float*)d_in[6];
    const float* out_w    = (const float*)d_in[7];
    const float* out_b    = (const float*)d_in[8];
    const float* bn_gamma = (const float*)d_in[9];
    const float* bn_beta  = (const float*)d_in[10];
    float* out = (float*)d_out;

    zero_stats<<<1, 64>>>();
    qkv_kernel<<<dim3(128, BB), 128>>>(x, g_w, g_b, theta_w, theta_b, phi_w, phi_b);
    attn_kernel<<<dim3(64, BB), 256>>>();
    fuse_kernel<<<1024, 256>>>(x, out_w, out_b, out);
    stats_kernel<<<dim3(C, 8), 256>>>(out);
    finalize_kernel<<<1, 64>>>(bn_gamma, bn_beta);
    norm_kernel<<<4096, 256>>>(out);
}

// round 4
// speedup vs baseline: 2.0742x; 1.0518x over previous
#include <cuda_runtime.h>

#define BB 4
#define C 64
#define IC 16
#define H 128
#define W 128
#define DH 64
#define DW 64
#define NN 4096  // DH*DW

// ---------------- scratch (device globals; no allocation) ----------------
__device__ __align__(16) float g_q[BB*NN*IC];
__device__ __align__(16) float g_k[BB*NN*IC];
__device__ __align__(16) float g_v[BB*NN*IC];
__device__ __align__(16) float g_y[BB*IC*NN];
__device__ float g_sum[C];
__device__ float g_sqs[C];
__device__ float g_ab[2*C];   // scale, shift

typedef unsigned long long ull;

__device__ __forceinline__ ull pk2(float x, float y) {
    ull r;
    asm("mov.b64 %0, {%1,%2};" : "=l"(r) : "f"(x), "f"(y));
    return r;
}
__device__ __forceinline__ void upk2(ull v, float& lo, float& hi) {
    asm("mov.b64 {%0,%1}, %2;" : "=f"(lo), "=f"(hi) : "l"(v));
}
__device__ __forceinline__ void fma2(ull& d, ull a, ull b) {
    asm("fma.rn.f32x2 %0, %1, %2, %3;" : "=l"(d) : "l"(a), "l"(b), "l"(d));
}
__device__ __forceinline__ float ex2f(float x) {
    float r;
    asm("ex2.approx.f32 %0, %1;" : "=f"(r) : "f"(x));
    return r;
}

#define LOG2E 1.4426950408889634f

// ---------------- Kernel 1: downsample (odd-pixel pick) + Q/K/V projections ----------------
__global__ void qkv_kernel(const float* __restrict__ x,
                           const float* __restrict__ g_w,  const float* __restrict__ g_b,
                           const float* __restrict__ th_w, const float* __restrict__ th_b,
                           const float* __restrict__ ph_w, const float* __restrict__ ph_b) {
    __shared__ float xd_s[C][32];
    __shared__ float w_s[48][C];
    __shared__ float b_s[48];
    int b = blockIdx.y, tile = blockIdx.x, tid = threadIdx.x;

    if (b == 0 && tile == 0 && tid < C) { g_sum[tid] = 0.f; g_sqs[tid] = 0.f; }

    for (int idx = tid; idx < 48 * C; idx += 128) {
        int o = idx >> 6, c = idx & 63;
        float w;
        if (o < 16)      w = th_w[o * C + c];
        else if (o < 32) w = ph_w[(o - 16) * C + c];
        else             w = g_w[(o - 32) * C + c];
        w_s[o][c] = w;
    }
    if (tid < 48)
        b_s[tid] = (tid < 16) ? th_b[tid] : ((tid < 32) ? ph_b[tid - 16] : g_b[tid - 32]);

    int n0 = tile * 32;
    for (int idx = tid; idx < C * 32; idx += 128) {
        int c = idx >> 5, p = idx & 31;
        int n = n0 + p;
        int i = n >> 6, j = n & 63;
        xd_s[c][p] = x[(((b * C + c) * H + 2 * i + 1) * W) + 2 * j + 1];
    }
    __syncthreads();

    int p = tid & 31, og = tid >> 5;
    int n = n0 + p;
    #pragma unroll
    for (int r = 0; r < 12; r++) {
        int o = og + 4 * r;
        float a0 = b_s[o], a1 = 0.f, a2 = 0.f, a3 = 0.f;
        #pragma unroll
        for (int c = 0; c < C; c += 4) {
            a0 = fmaf(w_s[o][c + 0], xd_s[c + 0][p], a0);
            a1 = fmaf(w_s[o][c + 1], xd_s[c + 1][p], a1);
            a2 = fmaf(w_s[o][c + 2], xd_s[c + 2][p], a2);
            a3 = fmaf(w_s[o][c + 3], xd_s[c + 3][p], a3);
        }
        float acc = (a0 + a1) + (a2 + a3);
        if (o < 16)      g_q[(b * NN + n) * IC + o]        = acc;
        else if (o < 32) g_k[(b * NN + n) * IC + (o - 16)] = acc;
        else             g_v[(b * NN + n) * IC + (o - 32)] = acc;
    }
}

// ---------------- Kernel 2: register-blocked flash attention, v2 ----------------
// grid (64, BB), block 256, 2 CTAs/SM. 64 queries/block.
// Thread tile: 2 queries x 16 keys. kg = t>>5 (warp-uniform -> K/V smem broadcast).
#define TK 128
#define KSP 136   // ks row stride (floats), 16B-aligned rows
__global__ __launch_bounds__(256, 2) void attn_kernel() {
    __shared__ __align__(16) float ks[IC][KSP];
    __shared__ __align__(16) float vs[TK][IC];
    __shared__ float red[8][66];
    __shared__ float dsm[64];

    int b = blockIdx.y;
    int t = threadIdx.x;
    int qg = t & 31, kg = t >> 5;
    int n0 = blockIdx.x * 64;

    // preload this thread's 2 queries (pre-scaled by log2e)
    float q0[16], q1[16];
    {
        const float4* qp = (const float4*)(g_q + (b * NN + n0 + 2 * qg) * IC);
        #pragma unroll
        for (int i = 0; i < 4; i++) {
            float4 f = qp[i];
            q0[4*i+0] = f.x * LOG2E; q0[4*i+1] = f.y * LOG2E;
            q0[4*i+2] = f.z * LOG2E; q0[4*i+3] = f.w * LOG2E;
            f = qp[i + 4];
            q1[4*i+0] = f.x * LOG2E; q1[4*i+1] = f.y * LOG2E;
            q1[4*i+2] = f.z * LOG2E; q1[4*i+3] = f.w * LOG2E;
        }
    }

    ull Y0[8], Y1[8];
    #pragma unroll
    for (int i = 0; i < 8; i++) { Y0[i] = 0ull; Y1[i] = 0ull; }
    float den0 = 0.f, den1 = 0.f;

    const float4* kb = (const float4*)(g_k + b * NN * IC);
    const float4* vb = (const float4*)(g_v + b * NN * IC);

    for (int kt = 0; kt < NN; kt += TK) {
        __syncthreads();
        // stage K (transposed) and V (row-major): 512 float4 chunks each
        {
            int base = kt * 4;  // float4 index
            #pragma unroll
            for (int i = 0; i < 2; i++) {
                int idx = t + i * 256;
                int key = idx >> 2, ch = idx & 3;
                float4 kv = kb[base + idx];
                ks[ch * 4 + 0][key] = kv.x; ks[ch * 4 + 1][key] = kv.y;
                ks[ch * 4 + 2][key] = kv.z; ks[ch * 4 + 3][key] = kv.w;
                ((float4*)vs)[idx] = vb[base + idx];
            }
        }
        __syncthreads();

        // scores: S[2 queries][8 key-pairs]
        ull S0[8], S1[8];
        #pragma unroll
        for (int i = 0; i < 8; i++) { S0[i] = 0ull; S1[i] = 0ull; }

        #pragma unroll
        for (int ic = 0; ic < IC; ic++) {
            const ulonglong2* kr = (const ulonglong2*)&ks[ic][kg * 16];
            ulonglong2 ka = kr[0], kc = kr[1], ke = kr[2], kgg = kr[3];
            ull qa = pk2(q0[ic], q0[ic]);
            ull qb = pk2(q1[ic], q1[ic]);
            fma2(S0[0], qa, ka.x);  fma2(S0[1], qa, ka.y);
            fma2(S0[2], qa, kc.x);  fma2(S0[3], qa, kc.y);
            fma2(S0[4], qa, ke.x);  fma2(S0[5], qa, ke.y);
            fma2(S0[6], qa, kgg.x); fma2(S0[7], qa, kgg.y);
            fma2(S1[0], qb, ka.x);  fma2(S1[1], qb, ka.y);
            fma2(S1[2], qb, kc.x);  fma2(S1[3], qb, kc.y);
            fma2(S1[4], qb, ke.x);  fma2(S1[5], qb, ke.y);
            fma2(S1[6], qb, kgg.x); fma2(S1[7], qb, kgg.y);
        }

        // exp + PV
        #pragma unroll
        for (int p = 0; p < 8; p++) {
            float s00, s01, s10, s11;
            upk2(S0[p], s00, s01);
            upk2(S1[p], s10, s11);
            float e00 = ex2f(s00), e01 = ex2f(s01);
            float e10 = ex2f(s10), e11 = ex2f(s11);
            den0 += e00 + e01;
            den1 += e10 + e11;
            int k0 = kg * 16 + 2 * p;
            {
                const ulonglong2* vp = (const ulonglong2*)&vs[k0][0];
                ulonglong2 va = vp[0], vc = vp[1];
                ull ea = pk2(e00, e00), eb = pk2(e10, e10);
                fma2(Y0[0], ea, va.x); fma2(Y0[1], ea, va.y);
                fma2(Y0[2], ea, vc.x); fma2(Y0[3], ea, vc.y);
                fma2(Y1[0], eb, va.x); fma2(Y1[1], eb, va.y);
                fma2(Y1[2], eb, vc.x); fma2(Y1[3], eb, vc.y);
                ulonglong2 ve = vp[2], vg = vp[3];
                fma2(Y0[4], ea, ve.x); fma2(Y0[5], ea, ve.y);
                fma2(Y0[6], ea, vg.x); fma2(Y0[7], ea, vg.y);
                fma2(Y1[4], eb, ve.x); fma2(Y1[5], eb, ve.y);
                fma2(Y1[6], eb, vg.x); fma2(Y1[7], eb, vg.y);
            }
            {
                const ulonglong2* vp = (const ulonglong2*)&vs[k0 + 1][0];
                ulonglong2 va = vp[0], vc = vp[1];
                ull ea = pk2(e01, e01), eb = pk2(e11, e11);
                fma2(Y0[0], ea, va.x); fma2(Y0[1], ea, va.y);
                fma2(Y0[2], ea, vc.x); fma2(Y0[3], ea, vc.y);
                fma2(Y1[0], eb, va.x); fma2(Y1[1], eb, va.y);
                fma2(Y1[2], eb, vc.x); fma2(Y1[3], eb, vc.y);
                ulonglong2 ve = vp[2], vg = vp[3];
                fma2(Y0[4], ea, ve.x); fma2(Y0[5], ea, ve.y);
                fma2(Y0[6], ea, vg.x); fma2(Y0[7], ea, vg.y);
                fma2(Y1[4], eb, ve.x); fma2(Y1[5], eb, ve.y);
                fma2(Y1[6], eb, vg.x); fma2(Y1[7], eb, vg.y);
            }
        }
    }

    // ---- reduce across 8 key-groups ----
    __syncthreads();
    red[kg][2 * qg]     = den0;
    red[kg][2 * qg + 1] = den1;
    __syncthreads();
    if (t < 64) {
        float d = 0.f;
        #pragma unroll
        for (int k2 = 0; k2 < 8; k2++) d += red[k2][t];
        dsm[t] = 1.0f / d;
    }
    #pragma unroll
    for (int ic = 0; ic < IC; ic++) {
        __syncthreads();
        int p = ic >> 1, hf = ic & 1;
        float lo, hi;
        upk2(Y0[p], lo, hi);
        red[kg][2 * qg] = hf ? hi : lo;
        upk2(Y1[p], lo, hi);
        red[kg][2 * qg + 1] = hf ? hi : lo;
        __syncthreads();
        if (t < 64) {
            float s = 0.f;
            #pragma unroll
            for (int k2 = 0; k2 < 8; k2++) s += red[k2][t];
            g_y[(b * IC + ic) * NN + n0 + t] = s * dsm[t];
        }
    }
}

// ---------------- Kernel 3: upsample + out-proj + residual ----------------
__global__ void fuse_kernel(const float* __restrict__ x,
                            const float* __restrict__ out_w, const float* __restrict__ out_b,
                            float* __restrict__ out) {
    __shared__ float yup[IC][64];
    __shared__ float wsm[C * IC];
    __shared__ float bsm[C];
    int bx = blockIdx.x;
    int b  = bx >> 8;
    int row = (bx >> 1) & 127;
    int jh = bx & 1;
    int t = threadIdx.x;

    ((float4*)wsm)[t] = ((const float4*)out_w)[t];
    if (t < C) bsm[t] = out_b[t];

    float fi = 0.5f * row - 0.5f;
    int r0 = (int)floorf(fi);
    float wi = fi - (float)r0;
    int r1 = min(r0 + 1, DH - 1);
    r0 = max(r0, 0);

    for (int idx = t; idx < IC * 64; idx += 256) {
        int ic = idx >> 6, p = idx & 63;
        int j = jh * 64 + p;
        float fj = 0.5f * j - 0.5f;
        int c0 = (int)floorf(fj);
        float wj = fj - (float)c0;
        int c1 = min(c0 + 1, DW - 1);
        c0 = max(c0, 0);
        const float* yp = g_y + (b * IC + ic) * NN;
        float v00 = yp[r0 * DW + c0], v01 = yp[r0 * DW + c1];
        float v10 = yp[r1 * DW + c0], v11 = yp[r1 * DW + c1];
        yup[ic][p] = (1.f - wi) * fmaf(wj, v01 - v00, v00)
                   +        wi  * fmaf(wj, v11 - v10, v10);
    }
    __syncthreads();

    int p = t & 63, cg = t >> 6;
    float yr[16];
    #pragma unroll
    for (int i2 = 0; i2 < 16; i2++) yr[i2] = yup[i2][p];

    #pragma unroll
    for (int k = 0; k < 16; k++) {
        int c = cg * 16 + k;
        const float* wr = wsm + c * IC;
        float a0 = bsm[c], a1 = 0.f, a2 = 0.f, a3 = 0.f;
        #pragma unroll
        for (int i2 = 0; i2 < 16; i2 += 4) {
            a0 = fmaf(wr[i2 + 0], yr[i2 + 0], a0);
            a1 = fmaf(wr[i2 + 1], yr[i2 + 1], a1);
            a2 = fmaf(wr[i2 + 2], yr[i2 + 2], a2);
            a3 = fmaf(wr[i2 + 3], yr[i2 + 3], a3);
        }
        float acc = (a0 + a1) + (a2 + a3);
        int gi = ((b * C + c) * H + row) * W + jh * 64 + p;
        out[gi] = x[gi] + acc;
    }
}

// ---------------- Kernel 3b: BN batch stats over out ----------------
__global__ void stats_kernel(const float* __restrict__ out) {
    __shared__ float s1s[8], s2s[8];
    int c = blockIdx.x, sl = blockIdx.y, t = threadIdx.x;
    float s1 = 0.f, s2 = 0.f;
    #pragma unroll
    for (int b = 0; b < BB; b++) {
        const float4* p = (const float4*)(out + (((b * C + c) << 14) + sl * 2048));
        float4 v = p[t];
        s1 += (v.x + v.y) + (v.z + v.w);
        s2 += fmaf(v.x, v.x, v.y * v.y) + fmaf(v.z, v.z, v.w * v.w);
        v = p[t + 256];
        s1 += (v.x + v.y) + (v.z + v.w);
        s2 += fmaf(v.x, v.x, v.y * v.y) + fmaf(v.z, v.z, v.w * v.w);
    }
    #pragma unroll
    for (int off = 16; off; off >>= 1) {
        s1 += __shfl_down_sync(0xffffffffu, s1, off);
        s2 += __shfl_down_sync(0xffffffffu, s2, off);
    }
    int w = t >> 5;
    if ((t & 31) == 0) { s1s[w] = s1; s2s[w] = s2; }
    __syncthreads();
    if (t == 0) {
        float a1 = 0.f, a2 = 0.f;
        #pragma unroll
        for (int i = 0; i < 8; i++) { a1 += s1s[i]; a2 += s2s[i]; }
        atomicAdd(&g_sum[c], a1);
        atomicAdd(&g_sqs[c], a2);
    }
}

// ---------------- Kernel 4: finalize BN scale/shift ----------------
__global__ void finalize_kernel(const float* __restrict__ bn_gamma,
                                const float* __restrict__ bn_beta) {
    int c = threadIdx.x;
    if (c < C) {
        float npix = (float)(BB * H * W);
        float mean = g_sum[c] / npix;
        float var  = g_sqs[c] / npix - mean * mean;
        float rstd = rsqrtf(var + 1e-5f);
        float a = bn_gamma[c] * rstd;
        g_ab[c] = a;
        g_ab[C + c] = bn_beta[c] - mean * a;
    }
}

// ---------------- Kernel 5: apply BN affine in place ----------------
__global__ void norm_kernel(float* __restrict__ out) {
    int e4 = blockIdx.x * 256 + threadIdx.x;
    int e = e4 * 4;
    int c = (e >> 14) & 63;
    float a = g_ab[c], sh = g_ab[C + c];
    float4 v = *(float4*)(out + e);
    v.x = fmaf(v.x, a, sh);
    v.y = fmaf(v.y, a, sh);
    v.z = fmaf(v.z, a, sh);
    v.w = fmaf(v.w, a, sh);
    *(float4*)(out + e) = v;
}

// ---------------- launch ----------------
extern "C" void kernel_launch(void* const* d_in, const int* in_sizes, int n_in,
                              void* d_out, int out_size) {
    const float* x        = (const float*)d_in[0];
    const float* g_w      = (const float*)d_in[1];
    const float* g_b      = (const float*)d_in[2];
    const float* theta_w  = (const float*)d_in[3];
    const float* theta_b  = (const float*)d_in[4];
    const float* phi_w    = (const float*)d_in[5];
    const float* phi_b    = (const float*)d_in[6];
    const float* out_w    = (const float*)d_in[7];
    const float* out_b    = (const float*)d_in[8];
    const float* bn_gamma = (const float*)d_in[9];
    const float* bn_beta  = (const float*)d_in[10];
    float* out = (float*)d_out;

    qkv_kernel<<<dim3(128, BB), 128>>>(x, g_w, g_b, theta_w, theta_b, phi_w, phi_b);
    attn_kernel<<<dim3(64, BB), 256>>>();
    fuse_kernel<<<1024, 256>>>(x, out_w, out_b, out);
    stats_kernel<<<dim3(C, 8), 256>>>(out);
    finalize_kernel<<<1, 64>>>(bn_gamma, bn_beta);
    norm_kernel<<<4096, 256>>>(out);
}

// round 5
// speedup vs baseline: 2.2881x; 1.1031x over previous
#include <cuda_runtime.h>

#define BB 4
#define C 64
#define IC 16
#define H 128
#define W 128
#define DH 64
#define DW 64
#define NN 4096  // DH*DW

// ---------------- scratch (device globals; no allocation) ----------------
__device__ __align__(16) float g_q[BB*NN*IC];
__device__ __align__(16) float g_k[BB*NN*IC];
__device__ __align__(16) float g_v[BB*NN*IC];
__device__ __align__(16) float g_y[BB*IC*NN];
__device__ float g_sum[C];
__device__ float g_sqs[C];

typedef unsigned long long ull;
typedef unsigned int uint;

__device__ __forceinline__ ull pk2(float x, float y) {
    ull r;
    asm("mov.b64 %0, {%1,%2};" : "=l"(r) : "f"(x), "f"(y));
    return r;
}
__device__ __forceinline__ void upk2(ull v, float& lo, float& hi) {
    asm("mov.b64 {%0,%1}, %2;" : "=f"(lo), "=f"(hi) : "l"(v));
}
__device__ __forceinline__ void fma2(ull& d, ull a, ull b) {
    asm("fma.rn.f32x2 %0, %1, %2, %3;" : "=l"(d) : "l"(a), "l"(b), "l"(d));
}
__device__ __forceinline__ ull add2(ull a, ull b) {
    ull r;
    asm("add.rn.f32x2 %0, %1, %2;" : "=l"(r) : "l"(a), "l"(b));
    return r;
}
__device__ __forceinline__ float ex2f(float x) {
    float r;
    asm("ex2.approx.f32 %0, %1;" : "=f"(r) : "f"(x));
    return r;
}
__device__ __forceinline__ uint tf32c(float f) {
    uint r;
    asm("cvt.rna.tf32.f32 %0, %1;" : "=r"(r) : "f"(f));
    return r;
}
__device__ __forceinline__ void mma_tf32(float* c, const uint* a, uint b0, uint b1) {
    asm("mma.sync.aligned.m16n8k8.row.col.f32.tf32.tf32.f32 "
        "{%0,%1,%2,%3}, {%4,%5,%6,%7}, {%8,%9}, {%0,%1,%2,%3};"
        : "+f"(c[0]), "+f"(c[1]), "+f"(c[2]), "+f"(c[3])
        : "r"(a[0]), "r"(a[1]), "r"(a[2]), "r"(a[3]), "r"(b0), "r"(b1));
}

#define LOG2E 1.4426950408889634f

// ---------------- Kernel 1: downsample (odd-pixel pick) + Q/K/V projections ----------------
__global__ void qkv_kernel(const float* __restrict__ x,
                           const float* __restrict__ g_w,  const float* __restrict__ g_b,
                           const float* __restrict__ th_w, const float* __restrict__ th_b,
                           const float* __restrict__ ph_w, const float* __restrict__ ph_b) {
    __shared__ float xd_s[C][32];
    __shared__ float w_s[48][C];
    __shared__ float b_s[48];
    int b = blockIdx.y, tile = blockIdx.x, tid = threadIdx.x;

    if (b == 0 && tile == 0 && tid < C) { g_sum[tid] = 0.f; g_sqs[tid] = 0.f; }

    for (int idx = tid; idx < 48 * C; idx += 128) {
        int o = idx >> 6, c = idx & 63;
        float w;
        if (o < 16)      w = th_w[o * C + c];
        else if (o < 32) w = ph_w[(o - 16) * C + c];
        else             w = g_w[(o - 32) * C + c];
        w_s[o][c] = w;
    }
    if (tid < 48)
        b_s[tid] = (tid < 16) ? th_b[tid] : ((tid < 32) ? ph_b[tid - 16] : g_b[tid - 32]);

    int n0 = tile * 32;
    for (int idx = tid; idx < C * 32; idx += 128) {
        int c = idx >> 5, p = idx & 31;
        int n = n0 + p;
        int i = n >> 6, j = n & 63;
        xd_s[c][p] = x[(((b * C + c) * H + 2 * i + 1) * W) + 2 * j + 1];
    }
    __syncthreads();

    int p = tid & 31, og = tid >> 5;
    int n = n0 + p;
    #pragma unroll
    for (int r = 0; r < 12; r++) {
        int o = og + 4 * r;
        float a0 = b_s[o], a1 = 0.f, a2 = 0.f, a3 = 0.f;
        #pragma unroll
        for (int c = 0; c < C; c += 4) {
            a0 = fmaf(w_s[o][c + 0], xd_s[c + 0][p], a0);
            a1 = fmaf(w_s[o][c + 1], xd_s[c + 1][p], a1);
            a2 = fmaf(w_s[o][c + 2], xd_s[c + 2][p], a2);
            a3 = fmaf(w_s[o][c + 3], xd_s[c + 3][p], a3);
        }
        float acc = (a0 + a1) + (a2 + a3);
        if (o < 16)      g_q[(b * NN + n) * IC + o]        = acc;
        else if (o < 32) g_k[(b * NN + n) * IC + (o - 16)] = acc;
        else             g_v[(b * NN + n) * IC + (o - 32)] = acc;
    }
}

// ---------------- Kernel 2: flash attention, tf32 mma scores + scalar f32x2 PV ----------------
// grid (64, BB), block 256 (8 warps), 2 CTAs/SM. CTA = 64 queries.
// warp w: queries (w&3)*16..+15, key-half kh = w>>2 (64 keys of the 128-key tile).
#define TK 128
#define KSP 136
__global__ __launch_bounds__(256, 2) void attn_kernel() {
    __shared__ uint  ks[IC][KSP];         // K transposed, tf32 bits
    __shared__ __align__(16) float vs[TK][20];  // V rows, padded
    __shared__ float redY[2][64][17];
    __shared__ float redD[2][64];

    int b = blockIdx.y;
    int t = threadIdx.x;
    int w = t >> 5, lane = t & 31;
    int qw = w & 3, kh = w >> 2;
    int r = lane >> 2, cc = lane & 3;
    int n0 = blockIdx.x * 64;

    // A fragments (Q), prescaled by log2e, tf32. 2 k-steps (ic 0-7, 8-15).
    uint A0[4], A1[4];
    {
        const float* qb = g_q + (b * NN + n0 + qw * 16) * IC;
        A0[0] = tf32c(qb[ r      * IC + cc    ] * LOG2E);
        A0[1] = tf32c(qb[(r + 8) * IC + cc    ] * LOG2E);
        A0[2] = tf32c(qb[ r      * IC + cc + 4] * LOG2E);
        A0[3] = tf32c(qb[(r + 8) * IC + cc + 4] * LOG2E);
        A1[0] = tf32c(qb[ r      * IC + cc + 8] * LOG2E);
        A1[1] = tf32c(qb[(r + 8) * IC + cc + 8] * LOG2E);
        A1[2] = tf32c(qb[ r      * IC + cc + 12] * LOG2E);
        A1[3] = tf32c(qb[(r + 8) * IC + cc + 12] * LOG2E);
    }

    ull Y0[8], Y1[8];
    #pragma unroll
    for (int i = 0; i < 8; i++) { Y0[i] = 0ull; Y1[i] = 0ull; }
    float denr = 0.f, dens = 0.f;

    const float4* kb = (const float4*)(g_k + b * NN * IC);
    const float4* vb = (const float4*)(g_v + b * NN * IC);

    for (int kt = 0; kt < NN; kt += TK) {
        __syncthreads();
        // stage: thread handles (ch = idx>>7, key = idx&127); lanes -> consecutive keys
        #pragma unroll
        for (int i = 0; i < 2; i++) {
            int idx = t + 256 * i;
            int ch = idx >> 7, key = idx & 127;
            float4 kv = kb[(kt + key) * 4 + ch];
            ks[ch * 4 + 0][key] = tf32c(kv.x);
            ks[ch * 4 + 1][key] = tf32c(kv.y);
            ks[ch * 4 + 2][key] = tf32c(kv.z);
            ks[ch * 4 + 3][key] = tf32c(kv.w);
            float4 vv = vb[(kt + key) * 4 + ch];
            *(float4*)&vs[key][ch * 4] = vv;
        }
        __syncthreads();

        // scores: 8 n-tiles x (2 mma)
        float S[8][4];
        #pragma unroll
        for (int nt = 0; nt < 8; nt++) {
            S[nt][0] = 0.f; S[nt][1] = 0.f; S[nt][2] = 0.f; S[nt][3] = 0.f;
            int key0 = kh * 64 + nt * 8 + r;
            uint b0 = ks[cc][key0],     b1 = ks[cc + 4][key0];
            mma_tf32(S[nt], A0, b0, b1);
            b0 = ks[cc + 8][key0]; b1 = ks[cc + 12][key0];
            mma_tf32(S[nt], A1, b0, b1);
        }

        // exp + PV (scalar f32x2)
        #pragma unroll
        for (int nt = 0; nt < 8; nt++) {
            int kA = kh * 64 + nt * 8 + 2 * cc;
            float e0 = ex2f(S[nt][0]);   // (q=r,   key kA)
            float e1 = ex2f(S[nt][1]);   // (q=r,   key kA+1)
            float e2 = ex2f(S[nt][2]);   // (q=r+8, key kA)
            float e3 = ex2f(S[nt][3]);   // (q=r+8, key kA+1)
            denr += e0 + e1;
            dens += e2 + e3;
            {
                const ulonglong2* vp = (const ulonglong2*)&vs[kA][0];
                ulonglong2 va = vp[0], vb2 = vp[1], vc = vp[2], vd = vp[3];
                ull ea = pk2(e0, e0), eb = pk2(e2, e2);
                fma2(Y0[0], ea, va.x);  fma2(Y0[1], ea, va.y);
                fma2(Y0[2], ea, vb2.x); fma2(Y0[3], ea, vb2.y);
                fma2(Y0[4], ea, vc.x);  fma2(Y0[5], ea, vc.y);
                fma2(Y0[6], ea, vd.x);  fma2(Y0[7], ea, vd.y);
                fma2(Y1[0], eb, va.x);  fma2(Y1[1], eb, va.y);
                fma2(Y1[2], eb, vb2.x); fma2(Y1[3], eb, vb2.y);
                fma2(Y1[4], eb, vc.x);  fma2(Y1[5], eb, vc.y);
                fma2(Y1[6], eb, vd.x);  fma2(Y1[7], eb, vd.y);
            }
            {
                const ulonglong2* vp = (const ulonglong2*)&vs[kA + 1][0];
                ulonglong2 va = vp[0], vb2 = vp[1], vc = vp[2], vd = vp[3];
                ull ea = pk2(e1, e1), eb = pk2(e3, e3);
                fma2(Y0[0], ea, va.x);  fma2(Y0[1], ea, va.y);
                fma2(Y0[2], ea, vb2.x); fma2(Y0[3], ea, vb2.y);
                fma2(Y0[4], ea, vc.x);  fma2(Y0[5], ea, vc.y);
                fma2(Y0[6], ea, vd.x);  fma2(Y0[7], ea, vd.y);
                fma2(Y1[0], eb, va.x);  fma2(Y1[1], eb, va.y);
                fma2(Y1[2], eb, vb2.x); fma2(Y1[3], eb, vb2.y);
                fma2(Y1[4], eb, vc.x);  fma2(Y1[5], eb, vc.y);
                fma2(Y1[6], eb, vd.x);  fma2(Y1[7], eb, vd.y);
            }
        }
    }

    // ---- in-warp reduce over cc (lanes xor 1, 2) ----
    #pragma unroll
    for (int i = 0; i < 8; i++) {
        Y0[i] = add2(Y0[i], __shfl_xor_sync(0xffffffffu, Y0[i], 1));
        Y0[i] = add2(Y0[i], __shfl_xor_sync(0xffffffffu, Y0[i], 2));
        Y1[i] = add2(Y1[i], __shfl_xor_sync(0xffffffffu, Y1[i], 1));
        Y1[i] = add2(Y1[i], __shfl_xor_sync(0xffffffffu, Y1[i], 2));
    }
    denr += __shfl_xor_sync(0xffffffffu, denr, 1);
    denr += __shfl_xor_sync(0xffffffffu, denr, 2);
    dens += __shfl_xor_sync(0xffffffffu, dens, 1);
    dens += __shfl_xor_sync(0xffffffffu, dens, 2);

    __syncthreads();   // vs reuse done; also orders redY writes below
    if (cc == 0) {
        int q0i = qw * 16 + r, q1i = q0i + 8;
        #pragma unroll
        for (int p = 0; p < 8; p++) {
            float lo, hi;
            upk2(Y0[p], lo, hi);
            redY[kh][q0i][2 * p] = lo; redY[kh][q0i][2 * p + 1] = hi;
            upk2(Y1[p], lo, hi);
            redY[kh][q1i][2 * p] = lo; redY[kh][q1i][2 * p + 1] = hi;
        }
        redD[kh][q0i] = denr;
        redD[kh][q1i] = dens;
    }
    __syncthreads();

    {
        int q = t >> 2, ic0 = (t & 3) * 4;
        float inv = 1.0f / (redD[0][q] + redD[1][q]);
        #pragma unroll
        for (int j = 0; j < 4; j++) {
            int ic = ic0 + j;
            float v = (redY[0][q][ic] + redY[1][q][ic]) * inv;
            g_y[(b * IC + ic) * NN + n0 + q] = v;
        }
    }
}

// ---------------- Kernel 3: upsample + out-proj + residual ----------------
__global__ void fuse_kernel(const float* __restrict__ x,
                            const float* __restrict__ out_w, const float* __restrict__ out_b,
                            float* __restrict__ out) {
    __shared__ float yup[IC][64];
    __shared__ float wsm[C * IC];
    __shared__ float bsm[C];
    int bx = blockIdx.x;
    int b  = bx >> 8;
    int row = (bx >> 1) & 127;
    int jh = bx & 1;
    int t = threadIdx.x;

    ((float4*)wsm)[t] = ((const float4*)out_w)[t];
    if (t < C) bsm[t] = out_b[t];

    float fi = 0.5f * row - 0.5f;
    int r0 = (int)floorf(fi);
    float wi = fi - (float)r0;
    int r1 = min(r0 + 1, DH - 1);
    r0 = max(r0, 0);

    for (int idx = t; idx < IC * 64; idx += 256) {
        int ic = idx >> 6, p = idx & 63;
        int j = jh * 64 + p;
        float fj = 0.5f * j - 0.5f;
        int c0 = (int)floorf(fj);
        float wj = fj - (float)c0;
        int c1 = min(c0 + 1, DW - 1);
        c0 = max(c0, 0);
        const float* yp = g_y + (b * IC + ic) * NN;
        float v00 = yp[r0 * DW + c0], v01 = yp[r0 * DW + c1];
        float v10 = yp[r1 * DW + c0], v11 = yp[r1 * DW + c1];
        yup[ic][p] = (1.f - wi) * fmaf(wj, v01 - v00, v00)
                   +        wi  * fmaf(wj, v11 - v10, v10);
    }
    __syncthreads();

    int p = t & 63, cg = t >> 6;
    float yr[16];
    #pragma unroll
    for (int i2 = 0; i2 < 16; i2++) yr[i2] = yup[i2][p];

    #pragma unroll
    for (int k = 0; k < 16; k++) {
        int c = cg * 16 + k;
        const float* wr = wsm + c * IC;
        float a0 = bsm[c], a1 = 0.f, a2 = 0.f, a3 = 0.f;
        #pragma unroll
        for (int i2 = 0; i2 < 16; i2 += 4) {
            a0 = fmaf(wr[i2 + 0], yr[i2 + 0], a0);
            a1 = fmaf(wr[i2 + 1], yr[i2 + 1], a1);
            a2 = fmaf(wr[i2 + 2], yr[i2 + 2], a2);
            a3 = fmaf(wr[i2 + 3], yr[i2 + 3], a3);
        }
        float acc = (a0 + a1) + (a2 + a3);
        int gi = ((b * C + c) * H + row) * W + jh * 64 + p;
        out[gi] = x[gi] + acc;
    }
}

// ---------------- Kernel 3b: BN batch stats over out ----------------
// grid (C, 16), block 256.
__global__ void stats_kernel(const float* __restrict__ out) {
    __shared__ float s1s[8], s2s[8];
    int c = blockIdx.x, sl = blockIdx.y, t = threadIdx.x;
    float s1 = 0.f, s2 = 0.f;
    #pragma unroll
    for (int b = 0; b < BB; b++) {
        const float4* p = (const float4*)(out + (((b * C + c) << 14) + sl * 1024));
        float4 v = p[t];
        s1 += (v.x + v.y) + (v.z + v.w);
        s2 += fmaf(v.x, v.x, v.y * v.y) + fmaf(v.z, v.z, v.w * v.w);
    }
    #pragma unroll
    for (int off = 16; off; off >>= 1) {
        s1 += __shfl_down_sync(0xffffffffu, s1, off);
        s2 += __shfl_down_sync(0xffffffffu, s2, off);
    }
    int w = t >> 5;
    if ((t & 31) == 0) { s1s[w] = s1; s2s[w] = s2; }
    __syncthreads();
    if (t == 0) {
        float a1 = 0.f, a2 = 0.f;
        #pragma unroll
        for (int i = 0; i < 8; i++) { a1 += s1s[i]; a2 += s2s[i]; }
        atomicAdd(&g_sum[c], a1);
        atomicAdd(&g_sqs[c], a2);
    }
}

// ---------------- Kernel 4: finalize + apply BN affine in place ----------------
__global__ void norm_kernel(float* __restrict__ out,
                            const float* __restrict__ bn_gamma,
                            const float* __restrict__ bn_beta) {
    int e4 = blockIdx.x * 256 + threadIdx.x;
    int e = e4 * 4;
    int c = (e >> 14) & 63;
    const float npix = (float)(BB * H * W);
    float mean = g_sum[c] / npix;
    float var  = g_sqs[c] / npix - mean * mean;
    float rstd = rsqrtf(var + 1e-5f);
    float a  = bn_gamma[c] * rstd;
    float sh = bn_beta[c] - mean * a;
    float4 v = *(float4*)(out + e);
    v.x = fmaf(v.x, a, sh);
    v.y = fmaf(v.y, a, sh);
    v.z = fmaf(v.z, a, sh);
    v.w = fmaf(v.w, a, sh);
    *(float4*)(out + e) = v;
}

// ---------------- launch ----------------
extern "C" void kernel_launch(void* const* d_in, const int* in_sizes, int n_in,
                              void* d_out, int out_size) {
    const float* x        = (const float*)d_in[0];
    const float* g_w      = (const float*)d_in[1];
    const float* g_b      = (const float*)d_in[2];
    const float* theta_w  = (const float*)d_in[3];
    const float* theta_b  = (const float*)d_in[4];
    const float* phi_w    = (const float*)d_in[5];
    const float* phi_b    = (const float*)d_in[6];
    const float* out_w    = (const float*)d_in[7];
    const float* out_b    = (const float*)d_in[8];
    const float* bn_gamma = (const float*)d_in[9];
    const float* bn_beta  = (const float*)d_in[10];
    float* out = (float*)d_out;

    qkv_kernel<<<dim3(128, BB), 128>>>(x, g_w, g_b, theta_w, theta_b, phi_w, phi_b);
    attn_kernel<<<dim3(64, BB), 256>>>();
    fuse_kernel<<<1024, 256>>>(x, out_w, out_b, out);
    stats_kernel<<<dim3(C, 16), 256>>>(out);
    norm_kernel<<<4096, 256>>>(out, bn_gamma, bn_beta);
}

// round 6
// speedup vs baseline: 3.6230x; 1.5834x over previous
#include <cuda_runtime.h>

#define BB 4
#define C 64
#define IC 16
#define H 128
#define W 128
#define DH 64
#define DW 64
#define NN 4096  // DH*DW

// ---------------- scratch (device globals; no allocation) ----------------
__device__ __align__(16) float g_q[BB*NN*IC];
__device__ __align__(16) float g_k[BB*NN*IC];
__device__ __align__(16) float g_v[BB*NN*IC];
__device__ __align__(16) float g_y[BB*IC*NN];
__device__ float g_sum[C];
__device__ float g_sqs[C];

typedef unsigned long long ull;
typedef unsigned int uint;

__device__ __forceinline__ ull pk2(float x, float y) {
    ull r;
    asm("mov.b64 %0, {%1,%2};" : "=l"(r) : "f"(x), "f"(y));
    return r;
}
__device__ __forceinline__ void upk2(ull v, float& lo, float& hi) {
    asm("mov.b64 {%0,%1}, %2;" : "=f"(lo), "=f"(hi) : "l"(v));
}
__device__ __forceinline__ void fma2(ull& d, ull a, ull b) {
    asm("fma.rn.f32x2 %0, %1, %2, %3;" : "=l"(d) : "l"(a), "l"(b), "l"(d));
}
__device__ __forceinline__ ull add2(ull a, ull b) {
    ull r;
    asm("add.rn.f32x2 %0, %1, %2;" : "=l"(r) : "l"(a), "l"(b));
    return r;
}
__device__ __forceinline__ float ex2f(float x) {
    float r;
    asm("ex2.approx.f32 %0, %1;" : "=f"(r) : "f"(x));
    return r;
}
__device__ __forceinline__ uint tf32c(float f) {
    uint r;
    asm("cvt.rna.tf32.f32 %0, %1;" : "=r"(r) : "f"(f));
    return r;
}
__device__ __forceinline__ void mma_tf32(float* c, const uint* a, uint b0, uint b1) {
    asm("mma.sync.aligned.m16n8k8.row.col.f32.tf32.tf32.f32 "
        "{%0,%1,%2,%3}, {%4,%5,%6,%7}, {%8,%9}, {%0,%1,%2,%3};"
        : "+f"(c[0]), "+f"(c[1]), "+f"(c[2]), "+f"(c[3])
        : "r"(a[0]), "r"(a[1]), "r"(a[2]), "r"(a[3]), "r"(b0), "r"(b1));
}

#define LOG2E 1.4426950408889634f

// ---------------- Kernel 1: downsample (odd-pixel pick) + Q/K/V projections ----------------
__global__ void qkv_kernel(const float* __restrict__ x,
                           const float* __restrict__ g_w,  const float* __restrict__ g_b,
                           const float* __restrict__ th_w, const float* __restrict__ th_b,
                           const float* __restrict__ ph_w, const float* __restrict__ ph_b) {
    __shared__ float xd_s[C][32];
    __shared__ float w_s[48][C];
    __shared__ float b_s[48];
    int b = blockIdx.y, tile = blockIdx.x, tid = threadIdx.x;

    if (b == 0 && tile == 0 && tid < C) { g_sum[tid] = 0.f; g_sqs[tid] = 0.f; }

    for (int idx = tid; idx < 48 * C; idx += 128) {
        int o = idx >> 6, c = idx & 63;
        float w;
        if (o < 16)      w = th_w[o * C + c];
        else if (o < 32) w = ph_w[(o - 16) * C + c];
        else             w = g_w[(o - 32) * C + c];
        w_s[o][c] = w;
    }
    if (tid < 48)
        b_s[tid] = (tid < 16) ? th_b[tid] : ((tid < 32) ? ph_b[tid - 16] : g_b[tid - 32]);

    int n0 = tile * 32;
    for (int idx = tid; idx < C * 32; idx += 128) {
        int c = idx >> 5, p = idx & 31;
        int n = n0 + p;
        int i = n >> 6, j = n & 63;
        xd_s[c][p] = x[(((b * C + c) * H + 2 * i + 1) * W) + 2 * j + 1];
    }
    __syncthreads();

    int p = tid & 31, og = tid >> 5;
    int n = n0 + p;
    #pragma unroll
    for (int r = 0; r < 12; r++) {
        int o = og + 4 * r;
        float a0 = b_s[o], a1 = 0.f, a2 = 0.f, a3 = 0.f;
        #pragma unroll
        for (int c = 0; c < C; c += 4) {
            a0 = fmaf(w_s[o][c + 0], xd_s[c + 0][p], a0);
            a1 = fmaf(w_s[o][c + 1], xd_s[c + 1][p], a1);
            a2 = fmaf(w_s[o][c + 2], xd_s[c + 2][p], a2);
            a3 = fmaf(w_s[o][c + 3], xd_s[c + 3][p], a3);
        }
        float acc = (a0 + a1) + (a2 + a3);
        if (o < 16)      g_q[(b * NN + n) * IC + o]        = acc;
        else if (o < 32) g_k[(b * NN + n) * IC + (o - 16)] = acc;
        else             g_v[(b * NN + n) * IC + (o - 32)] = acc;
    }
}

// ---------------- Kernel 2: full tensor-core flash attention ----------------
// grid (64, BB), block 256 (8 warps), 2 CTAs/SM. CTA = 64 queries.
// warp w: queries (w&3)*16..+15, key-half kh = w>>2.
// S via tf32 mma; P fed directly as next A-fragment via permuted key<->k-slot map
// (slot s = key 2s, slot s+4 = key 2s+1); V B-fragments loaded with same map.
#define TK 128
#define KSP 136
__global__ __launch_bounds__(256, 2) void attn_kernel() {
    __shared__ uint  ks[IC][KSP];               // K transposed, tf32 bits
    __shared__ __align__(16) float vs[TK][20];  // V rows, padded (conflict-free b-loads)
    __shared__ float redY[2][64][17];
    __shared__ float redD[2][64];

    int b = blockIdx.y;
    int t = threadIdx.x;
    int w = t >> 5, lane = t & 31;
    int qw = w & 3, kh = w >> 2;
    int r = lane >> 2, cc = lane & 3;
    int n0 = blockIdx.x * 64;

    // A fragments (Q), prescaled by log2e, tf32. 2 k-steps (ic 0-7, 8-15).
    uint A0[4], A1[4];
    {
        const float* qb = g_q + (b * NN + n0 + qw * 16) * IC;
        A0[0] = tf32c(qb[ r      * IC + cc     ] * LOG2E);
        A0[1] = tf32c(qb[(r + 8) * IC + cc     ] * LOG2E);
        A0[2] = tf32c(qb[ r      * IC + cc + 4 ] * LOG2E);
        A0[3] = tf32c(qb[(r + 8) * IC + cc + 4 ] * LOG2E);
        A1[0] = tf32c(qb[ r      * IC + cc + 8 ] * LOG2E);
        A1[1] = tf32c(qb[(r + 8) * IC + cc + 8 ] * LOG2E);
        A1[2] = tf32c(qb[ r      * IC + cc + 12] * LOG2E);
        A1[3] = tf32c(qb[(r + 8) * IC + cc + 12] * LOG2E);
    }

    // PV accumulators: C fragments for ic 0-7 (Y0) and ic 8-15 (Y1)
    float Y0[4] = {0.f, 0.f, 0.f, 0.f};
    float Y1[4] = {0.f, 0.f, 0.f, 0.f};
    float denr = 0.f, dens = 0.f;

    const float4* kb = (const float4*)(g_k + b * NN * IC);
    const float4* vb = (const float4*)(g_v + b * NN * IC);

    for (int kt = 0; kt < NN; kt += TK) {
        __syncthreads();
        #pragma unroll
        for (int i = 0; i < 2; i++) {
            int idx = t + 256 * i;
            int ch = idx >> 7, key = idx & 127;
            float4 kv = kb[(kt + key) * 4 + ch];
            ks[ch * 4 + 0][key] = tf32c(kv.x);
            ks[ch * 4 + 1][key] = tf32c(kv.y);
            ks[ch * 4 + 2][key] = tf32c(kv.z);
            ks[ch * 4 + 3][key] = tf32c(kv.w);
            float4 vv = vb[(kt + key) * 4 + ch];
            *(float4*)&vs[key][ch * 4] = vv;
        }
        __syncthreads();

        #pragma unroll
        for (int nt = 0; nt < 8; nt++) {
            int key0 = kh * 64 + nt * 8;
            // scores (16q x 8k), 2 k-steps over ic
            float S[4] = {0.f, 0.f, 0.f, 0.f};
            mma_tf32(S, A0, ks[cc][key0 + r],     ks[cc + 4][key0 + r]);
            mma_tf32(S, A1, ks[cc + 8][key0 + r], ks[cc + 12][key0 + r]);

            float e0 = ex2f(S[0]);   // (q=r,   key key0+2cc)
            float e1 = ex2f(S[1]);   // (q=r,   key key0+2cc+1)
            float e2 = ex2f(S[2]);   // (q=r+8, key key0+2cc)
            float e3 = ex2f(S[3]);   // (q=r+8, key key0+2cc+1)
            denr += e0 + e1;
            dens += e2 + e3;

            // P as A-fragment (permuted k-slot map); raw fp32 bits -> tf32 trunc
            uint P[4];
            P[0] = __float_as_uint(e0);   // A[r][slot cc]      = key key0+2cc
            P[1] = __float_as_uint(e2);   // A[r+8][slot cc]
            P[2] = __float_as_uint(e1);   // A[r][slot cc+4]    = key key0+2cc+1
            P[3] = __float_as_uint(e3);   // A[r+8][slot cc+4]
            int ka = key0 + 2 * cc;
            // B fragments: b0 = V[slot cc][n] = V[key0+2cc][ic], b1 = V[key0+2cc+1][ic]
            mma_tf32(Y0, P, __float_as_uint(vs[ka][r]),     __float_as_uint(vs[ka + 1][r]));
            mma_tf32(Y1, P, __float_as_uint(vs[ka][r + 8]), __float_as_uint(vs[ka + 1][r + 8]));
        }
    }

    // denominator: sum over the cc quad (keys mod 8 partition)
    denr += __shfl_xor_sync(0xffffffffu, denr, 1);
    denr += __shfl_xor_sync(0xffffffffu, denr, 2);
    dens += __shfl_xor_sync(0xffffffffu, dens, 1);
    dens += __shfl_xor_sync(0xffffffffu, dens, 2);

    __syncthreads();
    {
        int q0 = qw * 16 + r, q1 = q0 + 8;
        redY[kh][q0][2 * cc]     = Y0[0];
        redY[kh][q0][2 * cc + 1] = Y0[1];
        redY[kh][q1][2 * cc]     = Y0[2];
        redY[kh][q1][2 * cc + 1] = Y0[3];
        redY[kh][q0][8 + 2 * cc]     = Y1[0];
        redY[kh][q0][8 + 2 * cc + 1] = Y1[1];
        redY[kh][q1][8 + 2 * cc]     = Y1[2];
        redY[kh][q1][8 + 2 * cc + 1] = Y1[3];
        if (cc == 0) {
            redD[kh][q0] = denr;
            redD[kh][q1] = dens;
        }
    }
    __syncthreads();

    {
        int q = t >> 2, ic0 = (t & 3) * 4;
        float inv = 1.0f / (redD[0][q] + redD[1][q]);
        #pragma unroll
        for (int j = 0; j < 4; j++) {
            int ic = ic0 + j;
            float v = (redY[0][q][ic] + redY[1][q][ic]) * inv;
            g_y[(b * IC + ic) * NN + n0 + q] = v;
        }
    }
}

// ---------------- Kernel 3: upsample + out-proj + residual (f32x2) ----------------
// grid 1024, block 256. Tile = 64 output pixels (half row) x 64 channels.
// Thread: 2 adjacent pixels x 8 channels via packed fma2.
__global__ void fuse_kernel(const float* __restrict__ x,
                            const float* __restrict__ out_w, const float* __restrict__ out_b,
                            float* __restrict__ out) {
    __shared__ __align__(8) float yup[IC][64];
    __shared__ ull wsm2[C][IC];
    __shared__ float bsm[C];
    int bx = blockIdx.x;
    int b  = bx >> 8;
    int row = (bx >> 1) & 127;
    int jh = bx & 1;
    int t = threadIdx.x;

    #pragma unroll
    for (int i = 0; i < 4; i++) {
        int idx = t + 256 * i;
        float wv = out_w[idx];
        wsm2[idx >> 4][idx & 15] = pk2(wv, wv);
    }
    if (t < C) bsm[t] = out_b[t];

    float fi = 0.5f * row - 0.5f;
    int r0 = (int)floorf(fi);
    float wi = fi - (float)r0;
    int r1 = min(r0 + 1, DH - 1);
    r0 = max(r0, 0);

    for (int idx = t; idx < IC * 64; idx += 256) {
        int ic = idx >> 6, p = idx & 63;
        int j = jh * 64 + p;
        float fj = 0.5f * j - 0.5f;
        int c0 = (int)floorf(fj);
        float wj = fj - (float)c0;
        int c1 = min(c0 + 1, DW - 1);
        c0 = max(c0, 0);
        const float* yp = g_y + (b * IC + ic) * NN;
        float v00 = yp[r0 * DW + c0], v01 = yp[r0 * DW + c1];
        float v10 = yp[r1 * DW + c0], v11 = yp[r1 * DW + c1];
        yup[ic][p] = (1.f - wi) * fmaf(wj, v01 - v00, v00)
                   +        wi  * fmaf(wj, v11 - v10, v10);
    }
    __syncthreads();

    int p2 = t & 31, cg = t >> 5;      // pixel pair index, channel group (8 ch)
    ull yv[16];
    #pragma unroll
    for (int i2 = 0; i2 < 16; i2++) yv[i2] = *(const ull*)&yup[i2][2 * p2];

    #pragma unroll
    for (int k = 0; k < 8; k++) {
        int c = cg * 8 + k;
        float bb = bsm[c];
        ull acc = pk2(bb, bb);
        #pragma unroll
        for (int i2 = 0; i2 < 16; i2++) fma2(acc, wsm2[c][i2], yv[i2]);
        int gi = ((b * C + c) * H + row) * W + jh * 64 + 2 * p2;
        ull xv = *(const ull*)(x + gi);
        acc = add2(acc, xv);
        *(ull*)(out + gi) = acc;
    }
}

// ---------------- Kernel 3b: BN batch stats over out ----------------
__global__ void stats_kernel(const float* __restrict__ out) {
    __shared__ float s1s[8], s2s[8];
    int c = blockIdx.x, sl = blockIdx.y, t = threadIdx.x;
    float s1 = 0.f, s2 = 0.f;
    #pragma unroll
    for (int b = 0; b < BB; b++) {
        const float4* p = (const float4*)(out + (((b * C + c) << 14) + sl * 1024));
        float4 v = p[t];
        s1 += (v.x + v.y) + (v.z + v.w);
        s2 += fmaf(v.x, v.x, v.y * v.y) + fmaf(v.z, v.z, v.w * v.w);
    }
    #pragma unroll
    for (int off = 16; off; off >>= 1) {
        s1 += __shfl_down_sync(0xffffffffu, s1, off);
        s2 += __shfl_down_sync(0xffffffffu, s2, off);
    }
    int w = t >> 5;
    if ((t & 31) == 0) { s1s[w] = s1; s2s[w] = s2; }
    __syncthreads();
    if (t == 0) {
        float a1 = 0.f, a2 = 0.f;
        #pragma unroll
        for (int i = 0; i < 8; i++) { a1 += s1s[i]; a2 += s2s[i]; }
        atomicAdd(&g_sum[c], a1);
        atomicAdd(&g_sqs[c], a2);
    }
}

// ---------------- Kernel 4: finalize + apply BN affine in place ----------------
__global__ void norm_kernel(float* __restrict__ out,
                            const float* __restrict__ bn_gamma,
                            const float* __restrict__ bn_beta) {
    int e4 = blockIdx.x * 256 + threadIdx.x;
    int e = e4 * 4;
    int c = (e >> 14) & 63;
    const float npix = (float)(BB * H * W);
    float mean = g_sum[c] / npix;
    float var  = g_sqs[c] / npix - mean * mean;
    float rstd = rsqrtf(var + 1e-5f);
    float a  = bn_gamma[c] * rstd;
    float sh = bn_beta[c] - mean * a;
    float4 v = *(float4*)(out + e);
    v.x = fmaf(v.x, a, sh);
    v.y = fmaf(v.y, a, sh);
    v.z = fmaf(v.z, a, sh);
    v.w = fmaf(v.w, a, sh);
    *(float4*)(out + e) = v;
}

// ---------------- launch ----------------
extern "C" void kernel_launch(void* const* d_in, const int* in_sizes, int n_in,
                              void* d_out, int out_size) {
    const float* x        = (const float*)d_in[0];
    const float* g_w      = (const float*)d_in[1];
    const float* g_b      = (const float*)d_in[2];
    const float* theta_w  = (const float*)d_in[3];
    const float* theta_b  = (const float*)d_in[4];
    const float* phi_w    = (const float*)d_in[5];
    const float* phi_b    = (const float*)d_in[6];
    const float* out_w    = (const float*)d_in[7];
    const float* out_b    = (const float*)d_in[8];
    const float* bn_gamma = (const float*)d_in[9];
    const float* bn_beta  = (const float*)d_in[10];
    float* out = (float*)d_out;

    qkv_kernel<<<dim3(128, BB), 128>>>(x, g_w, g_b, theta_w, theta_b, phi_w, phi_b);
    attn_kernel<<<dim3(64, BB), 256>>>();
    fuse_kernel<<<1024, 256>>>(x, out_w, out_b, out);
    stats_kernel<<<dim3(C, 16), 256>>>(out);
    norm_kernel<<<4096, 256>>>(out, bn_gamma, bn_beta);
}

// round 7
// speedup vs baseline: 4.1764x; 1.1527x over previous
#include <cuda_runtime.h>

#define BB 4
#define C 64
#define IC 16
#define H 128
#define W 128
#define DH 64
#define DW 64
#define NN 4096  // DH*DW

// ---------------- scratch (device globals; no allocation) ----------------
__device__ __align__(16) float g_q[BB*NN*IC];
__device__ __align__(16) float g_k[BB*IC*NN];   // transposed [b][ic][n], tf32 bits
__device__ __align__(16) float g_v[BB*NN*IC];
__device__ __align__(16) float g_y[BB*IC*NN];
__device__ float g_sum[C];
__device__ float g_sqs[C];

typedef unsigned long long ull;
typedef unsigned int uint;

__device__ __forceinline__ ull pk2(float x, float y) {
    ull r;
    asm("mov.b64 %0, {%1,%2};" : "=l"(r) : "f"(x), "f"(y));
    return r;
}
__device__ __forceinline__ void fma2(ull& d, ull a, ull b) {
    asm("fma.rn.f32x2 %0, %1, %2, %3;" : "=l"(d) : "l"(a), "l"(b), "l"(d));
}
__device__ __forceinline__ ull add2(ull a, ull b) {
    ull r;
    asm("add.rn.f32x2 %0, %1, %2;" : "=l"(r) : "l"(a), "l"(b));
    return r;
}
__device__ __forceinline__ float ex2f(float x) {
    float r;
    asm("ex2.approx.f32 %0, %1;" : "=f"(r) : "f"(x));
    return r;
}
__device__ __forceinline__ uint tf32c(float f) {
    uint r;
    asm("cvt.rna.tf32.f32 %0, %1;" : "=r"(r) : "f"(f));
    return r;
}
__device__ __forceinline__ void mma_tf32(float* c, const uint* a, uint b0, uint b1) {
    asm("mma.sync.aligned.m16n8k8.row.col.f32.tf32.tf32.f32 "
        "{%0,%1,%2,%3}, {%4,%5,%6,%7}, {%8,%9}, {%0,%1,%2,%3};"
        : "+f"(c[0]), "+f"(c[1]), "+f"(c[2]), "+f"(c[3])
        : "r"(a[0]), "r"(a[1]), "r"(a[2]), "r"(a[3]), "r"(b0), "r"(b1));
}
__device__ __forceinline__ void cpa16(uint dst, const void* src) {
    asm volatile("cp.async.ca.shared.global [%0], [%1], 16;" :: "r"(dst), "l"(src));
}

#define LOG2E 1.4426950408889634f

// ---------------- Kernel 1: downsample (odd-pixel pick) + Q/K/V projections ----------------
__global__ void qkv_kernel(const float* __restrict__ x,
                           const float* __restrict__ g_w,  const float* __restrict__ g_b,
                           const float* __restrict__ th_w, const float* __restrict__ th_b,
                           const float* __restrict__ ph_w, const float* __restrict__ ph_b) {
    __shared__ float xd_s[C][32];
    __shared__ float w_s[48][C];
    __shared__ float b_s[48];
    int b = blockIdx.y, tile = blockIdx.x, tid = threadIdx.x;

    if (b == 0 && tile == 0 && tid < C) { g_sum[tid] = 0.f; g_sqs[tid] = 0.f; }

    for (int idx = tid; idx < 48 * C; idx += 128) {
        int o = idx >> 6, c = idx & 63;
        float w;
        if (o < 16)      w = th_w[o * C + c];
        else if (o < 32) w = ph_w[(o - 16) * C + c];
        else             w = g_w[(o - 32) * C + c];
        w_s[o][c] = w;
    }
    if (tid < 48)
        b_s[tid] = (tid < 16) ? th_b[tid] : ((tid < 32) ? ph_b[tid - 16] : g_b[tid - 32]);

    int n0 = tile * 32;
    for (int idx = tid; idx < C * 32; idx += 128) {
        int c = idx >> 5, p = idx & 31;
        int n = n0 + p;
        int i = n >> 6, j = n & 63;
        xd_s[c][p] = x[(((b * C + c) * H + 2 * i + 1) * W) + 2 * j + 1];
    }
    __syncthreads();

    int p = tid & 31, og = tid >> 5;
    int n = n0 + p;
    #pragma unroll
    for (int r = 0; r < 12; r++) {
        int o = og + 4 * r;
        float a0 = b_s[o], a1 = 0.f, a2 = 0.f, a3 = 0.f;
        #pragma unroll
        for (int c = 0; c < C; c += 4) {
            a0 = fmaf(w_s[o][c + 0], xd_s[c + 0][p], a0);
            a1 = fmaf(w_s[o][c + 1], xd_s[c + 1][p], a1);
            a2 = fmaf(w_s[o][c + 2], xd_s[c + 2][p], a2);
            a3 = fmaf(w_s[o][c + 3], xd_s[c + 3][p], a3);
        }
        float acc = (a0 + a1) + (a2 + a3);
        if (o < 16)      g_q[(b * NN + n) * IC + o] = acc;
        else if (o < 32) g_k[(b * IC + (o - 16)) * NN + n] = __uint_as_float(tf32c(acc));
        else             g_v[(b * NN + n) * IC + (o - 32)] = acc;
    }
}

// ---------------- Kernel 2: tensor-core flash attention, cp.async double-buffered ----------------
// grid (64, BB), block 256 (8 warps), 2 CTAs/SM. CTA = 64 queries.
// warp w: queries (w&3)*16..+15, key-half kh = w>>2.
#define TK 128
#define KSP 136
__global__ __launch_bounds__(256, 2) void attn_kernel() {
    __shared__ uint  ks[2][IC][KSP];                // K tf32 bits, [ic][key]
    __shared__ __align__(16) float vs[2][TK][20];   // V rows, padded
    __shared__ float redY[2][64][17];
    __shared__ float redD[2][64];

    int b = blockIdx.y;
    int t = threadIdx.x;
    int w = t >> 5, lane = t & 31;
    int qw = w & 3, kh = w >> 2;
    int r = lane >> 2, cc = lane & 3;
    int n0 = blockIdx.x * 64;

    // A fragments (Q), prescaled by log2e, tf32.
    uint A0[4], A1[4];
    {
        const float* qb = g_q + (b * NN + n0 + qw * 16) * IC;
        A0[0] = tf32c(qb[ r      * IC + cc     ] * LOG2E);
        A0[1] = tf32c(qb[(r + 8) * IC + cc     ] * LOG2E);
        A0[2] = tf32c(qb[ r      * IC + cc + 4 ] * LOG2E);
        A0[3] = tf32c(qb[(r + 8) * IC + cc + 4 ] * LOG2E);
        A1[0] = tf32c(qb[ r      * IC + cc + 8 ] * LOG2E);
        A1[1] = tf32c(qb[(r + 8) * IC + cc + 8 ] * LOG2E);
        A1[2] = tf32c(qb[ r      * IC + cc + 12] * LOG2E);
        A1[3] = tf32c(qb[(r + 8) * IC + cc + 12] * LOG2E);
    }

    float Y0[4] = {0.f, 0.f, 0.f, 0.f};
    float Y1[4] = {0.f, 0.f, 0.f, 0.f};
    float denr = 0.f, dens = 0.f;

    const float* kb = g_k + b * IC * NN;
    const float* vb = g_v + b * NN * IC;

    // per-thread staging addresses: 2 K chunks + 2 V chunks of 16B each
    int kc0 = t, kc1 = t + 256;          // K chunk ids (0..511): ic=c>>5, col4=c&31
    int ic0s = kc0 >> 5, col0 = kc0 & 31;
    int ic1s = kc1 >> 5, col1 = kc1 & 31;
    int vkey0 = t >> 2, vseg0 = t & 3;   // V chunk ids: key=c>>2, seg=c&3
    int vkey1 = (t + 256) >> 2, vseg1 = t & 3;

    uint ks_d0[2], ks_d1[2], vs_d0[2], vs_d1[2];
    #pragma unroll
    for (int bf = 0; bf < 2; bf++) {
        ks_d0[bf] = (uint)__cvta_generic_to_shared(&ks[bf][ic0s][col0 * 4]);
        ks_d1[bf] = (uint)__cvta_generic_to_shared(&ks[bf][ic1s][col1 * 4]);
        vs_d0[bf] = (uint)__cvta_generic_to_shared(&vs[bf][vkey0][vseg0 * 4]);
        vs_d1[bf] = (uint)__cvta_generic_to_shared(&vs[bf][vkey1][vseg1 * 4]);
    }

    // prologue: stage tile 0 into buffer 0
    cpa16(ks_d0[0], kb + ic0s * NN + col0 * 4);
    cpa16(ks_d1[0], kb + ic1s * NN + col1 * 4);
    cpa16(vs_d0[0], vb + vkey0 * IC + vseg0 * 4);
    cpa16(vs_d1[0], vb + vkey1 * IC + vseg1 * 4);
    asm volatile("cp.async.commit_group;");

    for (int it = 0; it < NN / TK; it++) {
        int cur = it & 1;
        if (it < NN / TK - 1) {
            int nxt = cur ^ 1, kt = (it + 1) * TK;
            cpa16(ks_d0[nxt], kb + ic0s * NN + kt + col0 * 4);
            cpa16(ks_d1[nxt], kb + ic1s * NN + kt + col1 * 4);
            cpa16(vs_d0[nxt], vb + (kt + vkey0) * IC + vseg0 * 4);
            cpa16(vs_d1[nxt], vb + (kt + vkey1) * IC + vseg1 * 4);
            asm volatile("cp.async.commit_group;");
            asm volatile("cp.async.wait_group 1;");
        } else {
            asm volatile("cp.async.wait_group 0;");
        }
        __syncthreads();

        #pragma unroll
        for (int nt = 0; nt < 8; nt++) {
            int key0 = kh * 64 + nt * 8;
            float S[4] = {0.f, 0.f, 0.f, 0.f};
            mma_tf32(S, A0, ks[cur][cc][key0 + r],     ks[cur][cc + 4][key0 + r]);
            mma_tf32(S, A1, ks[cur][cc + 8][key0 + r], ks[cur][cc + 12][key0 + r]);

            float e0 = ex2f(S[0]);
            float e1 = ex2f(S[1]);
            float e2 = ex2f(S[2]);
            float e3 = ex2f(S[3]);
            denr += e0 + e1;
            dens += e2 + e3;

            uint P[4];
            P[0] = __float_as_uint(e0);
            P[1] = __float_as_uint(e2);
            P[2] = __float_as_uint(e1);
            P[3] = __float_as_uint(e3);
            int ka = key0 + 2 * cc;
            mma_tf32(Y0, P, __float_as_uint(vs[cur][ka][r]),
                            __float_as_uint(vs[cur][ka + 1][r]));
            mma_tf32(Y1, P, __float_as_uint(vs[cur][ka][r + 8]),
                            __float_as_uint(vs[cur][ka + 1][r + 8]));
        }
        __syncthreads();   // compute done before this buffer is restaged
    }

    // denominator: sum over the cc quad
    denr += __shfl_xor_sync(0xffffffffu, denr, 1);
    denr += __shfl_xor_sync(0xffffffffu, denr, 2);
    dens += __shfl_xor_sync(0xffffffffu, dens, 1);
    dens += __shfl_xor_sync(0xffffffffu, dens, 2);

    {
        int q0 = qw * 16 + r, q1 = q0 + 8;
        redY[kh][q0][2 * cc]     = Y0[0];
        redY[kh][q0][2 * cc + 1] = Y0[1];
        redY[kh][q1][2 * cc]     = Y0[2];
        redY[kh][q1][2 * cc + 1] = Y0[3];
        redY[kh][q0][8 + 2 * cc]     = Y1[0];
        redY[kh][q0][8 + 2 * cc + 1] = Y1[1];
        redY[kh][q1][8 + 2 * cc]     = Y1[2];
        redY[kh][q1][8 + 2 * cc + 1] = Y1[3];
        if (cc == 0) {
            redD[kh][q0] = denr;
            redD[kh][q1] = dens;
        }
    }
    __syncthreads();

    {
        int q = t >> 2, ic = (t & 3) * 4;
        float inv = 1.0f / (redD[0][q] + redD[1][q]);
        #pragma unroll
        for (int j = 0; j < 4; j++) {
            float v = (redY[0][q][ic + j] + redY[1][q][ic + j]) * inv;
            g_y[(b * IC + ic + j) * NN + n0 + q] = v;
        }
    }
}

// ---------------- Kernel 3: upsample + out-proj + residual (f32x2) ----------------
__global__ void fuse_kernel(const float* __restrict__ x,
                            const float* __restrict__ out_w, const float* __restrict__ out_b,
                            float* __restrict__ out) {
    __shared__ __align__(8) float yup[IC][64];
    __shared__ ull wsm2[C][IC];
    __shared__ float bsm[C];
    int bx = blockIdx.x;
    int b  = bx >> 8;
    int row = (bx >> 1) & 127;
    int jh = bx & 1;
    int t = threadIdx.x;

    #pragma unroll
    for (int i = 0; i < 4; i++) {
        int idx = t + 256 * i;
        float wv = out_w[idx];
        wsm2[idx >> 4][idx & 15] = pk2(wv, wv);
    }
    if (t < C) bsm[t] = out_b[t];

    float fi = 0.5f * row - 0.5f;
    int r0 = (int)floorf(fi);
    float wi = fi - (float)r0;
    int r1 = min(r0 + 1, DH - 1);
    r0 = max(r0, 0);

    for (int idx = t; idx < IC * 64; idx += 256) {
        int ic = idx >> 6, p = idx & 63;
        int j = jh * 64 + p;
        float fj = 0.5f * j - 0.5f;
        int c0 = (int)floorf(fj);
        float wj = fj - (float)c0;
        int c1 = min(c0 + 1, DW - 1);
        c0 = max(c0, 0);
        const float* yp = g_y + (b * IC + ic) * NN;
        float v00 = yp[r0 * DW + c0], v01 = yp[r0 * DW + c1];
        float v10 = yp[r1 * DW + c0], v11 = yp[r1 * DW + c1];
        yup[ic][p] = (1.f - wi) * fmaf(wj, v01 - v00, v00)
                   +        wi  * fmaf(wj, v11 - v10, v10);
    }
    __syncthreads();

    int p2 = t & 31, cg = t >> 5;
    ull yv[16];
    #pragma unroll
    for (int i2 = 0; i2 < 16; i2++) yv[i2] = *(const ull*)&yup[i2][2 * p2];

    #pragma unroll
    for (int k = 0; k < 8; k++) {
        int c = cg * 8 + k;
        float bb = bsm[c];
        ull acc = pk2(bb, bb);
        #pragma unroll
        for (int i2 = 0; i2 < 16; i2++) fma2(acc, wsm2[c][i2], yv[i2]);
        int gi = ((b * C + c) * H + row) * W + jh * 64 + 2 * p2;
        ull xv = *(const ull*)(x + gi);
        acc = add2(acc, xv);
        *(ull*)(out + gi) = acc;
    }
}

// ---------------- Kernel 3b: BN batch stats over out ----------------
__global__ void stats_kernel(const float* __restrict__ out) {
    __shared__ float s1s[8], s2s[8];
    int c = blockIdx.x, sl = blockIdx.y, t = threadIdx.x;
    float s1 = 0.f, s2 = 0.f;
    #pragma unroll
    for (int b = 0; b < BB; b++) {
        const float4* p = (const float4*)(out + (((b * C + c) << 14) + sl * 1024));
        float4 v = p[t];
        s1 += (v.x + v.y) + (v.z + v.w);
        s2 += fmaf(v.x, v.x, v.y * v.y) + fmaf(v.z, v.z, v.w * v.w);
    }
    #pragma unroll
    for (int off = 16; off; off >>= 1) {
        s1 += __shfl_down_sync(0xffffffffu, s1, off);
        s2 += __shfl_down_sync(0xffffffffu, s2, off);
    }
    int w = t >> 5;
    if ((t & 31) == 0) { s1s[w] = s1; s2s[w] = s2; }
    __syncthreads();
    if (t == 0) {
        float a1 = 0.f, a2 = 0.f;
        #pragma unroll
        for (int i = 0; i < 8; i++) { a1 += s1s[i]; a2 += s2s[i]; }
        atomicAdd(&g_sum[c], a1);
        atomicAdd(&g_sqs[c], a2);
    }
}

// ---------------- Kernel 4: finalize + apply BN affine in place ----------------
__global__ void norm_kernel(float* __restrict__ out,
                            const float* __restrict__ bn_gamma,
                            const float* __restrict__ bn_beta) {
    int e4 = blockIdx.x * 256 + threadIdx.x;
    int e = e4 * 4;
    int c = (e >> 14) & 63;
    const float npix = (float)(BB * H * W);
    float mean = g_sum[c] / npix;
    float var  = g_sqs[c] / npix - mean * mean;
    float rstd = rsqrtf(var + 1e-5f);
    float a  = bn_gamma[c] * rstd;
    float sh = bn_beta[c] - mean * a;
    float4 v = *(float4*)(out + e);
    v.x = fmaf(v.x, a, sh);
    v.y = fmaf(v.y, a, sh);
    v.z = fmaf(v.z, a, sh);
    v.w = fmaf(v.w, a, sh);
    *(float4*)(out + e) = v;
}

// ---------------- launch ----------------
extern "C" void kernel_launch(void* const* d_in, const int* in_sizes, int n_in,
                              void* d_out, int out_size) {
    const float* x        = (const float*)d_in[0];
    const float* g_w      = (const float*)d_in[1];
    const float* g_b      = (const float*)d_in[2];
    const float* theta_w  = (const float*)d_in[3];
    const float* theta_b  = (const float*)d_in[4];
    const float* phi_w    = (const float*)d_in[5];
    const float* phi_b    = (const float*)d_in[6];
    const float* out_w    = (const float*)d_in[7];
    const float* out_b    = (const float*)d_in[8];
    const float* bn_gamma = (const float*)d_in[9];
    const float* bn_beta  = (const float*)d_in[10];
    float* out = (float*)d_out;

    qkv_kernel<<<dim3(128, BB), 128>>>(x, g_w, g_b, theta_w, theta_b, phi_w, phi_b);
    attn_kernel<<<dim3(64, BB), 256>>>();
    fuse_kernel<<<1024, 256>>>(x, out_w, out_b, out);
    stats_kernel<<<dim3(C, 16), 256>>>(out);
    norm_kernel<<<4096, 256>>>(out, bn_gamma, bn_beta);
}